// round 7
// baseline (speedup 1.0000x reference)
#include <cuda_runtime.h>
#include <math.h>

#define B 2
#define NF 20000
#define NS 30000
#define C 128
#define NKEY 500
#define NROWS (B*NF)

// output layout (flattened, float32, in reference return order)
#define OUT_OFF  0        // (1000,128)
#define KVI_OFF  128000   // (1000,3)
#define HEAT_OFF 131000   // (40000,)
#define S10_OFF  171000   // (40000,10)
#define KC_OFF   571000   // (1000,)

// spatial binning params (cell > radius with wide margin -> 3x3 ring suffices)
#define DIM0 36
#define CELL0 3.0f
#define DIM1 22
#define CELL1 5.0f
#define NCELLMAX (DIM0*DIM0)   // 1296
#define CAP 192                // fixed per-cell capacity (avg 23 / 62; huge margin)

#define SENT 0xFFFFFFFFFFFFFFFFull

// ---------------- scratch (device globals; no allocs allowed) ----------------
// NOTE: g_cellcnt must be zero at entry of every kernel_launch call. Device
// globals are zero-initialized at load, and fuse_kernel (the last kernel in
// the stream, ordered after knn's final read) re-zeroes it each call.
__device__ float g_sig[NROWS];
__device__ int   g_cls[NROWS];
__device__ int   g_topk[B*NKEY];
__device__ float2 g_keyworld[B*NKEY];
__device__ float g_mf0[B*NKEY*C];
__device__ float g_mf1[B*NKEY*C];
__device__ int    g_cellcnt[2][B][NCELLMAX];
__device__ float4 g_cellpts[2][B][NCELLMAX*CAP];   // {wx, wy, idx-bits, 0}

__device__ __forceinline__ float worldc(int c, float stride) {
    // ((c + 0.5) * stride) * 0.075 + (-54), each op fp32-rounded, no contraction
    float t = __fadd_rn((float)c, 0.5f);
    t = __fmul_rn(t, stride);
    t = __fmul_rn(t, 0.075f);
    return __fadd_rn(t, -54.0f);
}

// ---------------- bins: single-pass build (counts pre-zeroed) ----------------
__global__ void bin_build_kernel(const int* __restrict__ ca, const int* __restrict__ cb) {
    int id = blockIdx.x * 256 + threadIdx.x;
    if (id >= 2 * B * NS) return;
    int src = id / (B * NS);
    int rem = id - src * (B * NS);
    int b = rem / NS, i = rem - b * NS;
    int2 cc = ((const int2*)(src == 0 ? ca : cb))[b * NS + i];
    float stride = (src == 0) ? 4.0f : 8.0f;
    float wx = worldc(cc.x, stride), wy = worldc(cc.y, stride);
    float cell = (src == 0) ? CELL0 : CELL1;
    int dim = (src == 0) ? DIM0 : DIM1;
    int cx = min(dim - 1, max(0, (int)floorf((wx + 54.0f) / cell)));
    int cy = min(dim - 1, max(0, (int)floorf((wy + 54.0f) / cell)));
    int cid = cy * dim + cx;
    int pos = atomicAdd(&g_cellcnt[src][b][cid], 1);
    if (pos < CAP)
        g_cellpts[src][b][cid * CAP + pos] =
            make_float4(wx, wy, __uint_as_float((unsigned)i), 0.f);
}

// ---------------- K1: heat MLP (40000 x 128 -> 128 relu -> 10) ----------------
// X tile in shared; W1 streamed from L2 (hot, 64KB) -> high occupancy.
#define SXS 132   // padded row stride for shared X/H
#define HEAT_SMEM ((64*SXS + 128*12 + 64*10) * 4)

__global__ void __launch_bounds__(256) heat_kernel(
    const float* __restrict__ X, const float* __restrict__ W1,
    const float* __restrict__ G1, const float* __restrict__ B1,
    const float* __restrict__ W2, const float* __restrict__ B2v,
    float* __restrict__ outF)
{
    extern __shared__ float sm[];
    float* sX  = sm;                     // 64 * SXS
    float* sW2 = sm + 64 * SXS;          // 128 * 12 (padded, cols>=10 zero)
    float* sS  = sW2 + 128 * 12;         // 64 * 10
    const int tid = threadIdx.x;
    const int rowbase = blockIdx.x * 64;

    // load X tile (64x128) into padded shared
    {
        const float4* s = (const float4*)(X + (size_t)rowbase * C);
        #pragma unroll
        for (int t = 0; t < 8; ++t) {
            int idx = tid + t * 256;         // 0..2047 float4s
            int row = idx >> 5, c4 = idx & 31;
            *(float4*)(sX + row * SXS + c4 * 4) = s[idx];
        }
    }
    // load W2 padded to 12 cols
    for (int t = tid; t < 128 * 12; t += 256) {
        int i = t / 12, c = t - i * 12;
        sW2[t] = (c < 10) ? W2[i * 10 + c] : 0.f;
    }
    __syncthreads();

    // 16 thread-rows x 16 thread-cols; 4x8 micro-tile per thread
    const int ty = tid >> 4, tx = tid & 15;
    const int r0 = ty * 4, c0 = tx * 8;
    float acc[4][8];
    #pragma unroll
    for (int i = 0; i < 4; ++i)
        #pragma unroll
        for (int j = 0; j < 8; ++j) acc[i][j] = 0.f;

    #pragma unroll 2
    for (int k = 0; k < 128; k += 4) {
        float4 w[8];
        #pragma unroll
        for (int kk = 0; kk < 4; ++kk) {
            w[2*kk]   = __ldg((const float4*)(W1 + (k + kk) * 128 + c0));
            w[2*kk+1] = __ldg((const float4*)(W1 + (k + kk) * 128 + c0 + 4));
        }
        float4 xr[4];
        #pragma unroll
        for (int i = 0; i < 4; ++i)
            xr[i] = *(const float4*)&sX[(r0 + i) * SXS + k];
        #pragma unroll
        for (int kk = 0; kk < 4; ++kk) {
            #pragma unroll
            for (int i = 0; i < 4; ++i) {
                float x = (kk == 0) ? xr[i].x : (kk == 1) ? xr[i].y
                        : (kk == 2) ? xr[i].z : xr[i].w;
                acc[i][0] += x * w[2*kk].x;   acc[i][1] += x * w[2*kk].y;
                acc[i][2] += x * w[2*kk].z;   acc[i][3] += x * w[2*kk].w;
                acc[i][4] += x * w[2*kk+1].x; acc[i][5] += x * w[2*kk+1].y;
                acc[i][6] += x * w[2*kk+1].z; acc[i][7] += x * w[2*kk+1].w;
            }
        }
    }
    float4 ga = *(const float4*)&G1[c0], gb = *(const float4*)&G1[c0 + 4];
    float4 ba = *(const float4*)&B1[c0], bb = *(const float4*)&B1[c0 + 4];
    float gv[8] = {ga.x, ga.y, ga.z, ga.w, gb.x, gb.y, gb.z, gb.w};
    float bv[8] = {ba.x, ba.y, ba.z, ba.w, bb.x, bb.y, bb.z, bb.w};
    __syncthreads();  // all reads of sX done; safe to overwrite with H
    #pragma unroll
    for (int i = 0; i < 4; ++i)
        #pragma unroll
        for (int j = 0; j < 8; ++j) {
            float h = acc[i][j] * gv[j] + bv[j];
            sX[(r0 + i) * SXS + c0 + j] = h > 0.f ? h : 0.f;
        }
    __syncthreads();

    // stage 2: scores10 = H @ W2 + b2  (2 threads per row, 5 cols each)
    if (tid < 128) {
        const int r = tid >> 1, hhalf = tid & 1;
        const int cc0 = hhalf * 5;
        float a[5] = {0.f, 0.f, 0.f, 0.f, 0.f};
        for (int i = 0; i < 128; ++i) {
            float hv = sX[r * SXS + i];
            #pragma unroll
            for (int q = 0; q < 5; ++q) a[q] += hv * sW2[i * 12 + cc0 + q];
        }
        #pragma unroll
        for (int q = 0; q < 5; ++q) {
            int c = cc0 + q;
            float v = a[q] + B2v[c];
            outF[S10_OFF + (size_t)(rowbase + r) * 10 + c] = v;
            sS[r * 10 + c] = v;
        }
    }
    __syncthreads();
    if (tid < 64) {
        int r = tid, row = rowbase + r;
        float m = -INFINITY; int a = 0;
        #pragma unroll
        for (int c = 0; c < 10; ++c) {
            float v = sS[r * 10 + c];
            if (v > m) { m = v; a = c; }   // first max wins (jnp.argmax)
        }
        outF[HEAT_OFF + row] = m;
        g_sig[row] = 1.f / (1.f + expf(-m));
        g_cls[row] = a;
    }
}

// ---------------- K2: per-batch top-500 (jax.lax.top_k semantics) ----------------
// register-resident binary search + rank-by-count output (no bitonic sort,
// no histogram atom contention).
#define VPT 20          // values per thread: 20*1024 >= NF
#define CANDMAX 2048
#define TOPK_SMEM (CANDMAX * 8)

__global__ void __launch_bounds__(1024) topk_kernel(
    const int* __restrict__ fusion_coords, float* __restrict__ outF)
{
    extern __shared__ unsigned char dsm[];
    unsigned long long* cand = (unsigned long long*)dsm;   // CANDMAX
    __shared__ int s_cnt[32];   // one counter per binary-search iteration
    __shared__ int s_n;
    const int tid = threadIdx.x;
    const int lane = tid & 31;
    const int b = blockIdx.x;

    // load scores into registers
    unsigned vals[VPT];
    #pragma unroll
    for (int t = 0; t < VPT; ++t) {
        int i = tid + t * 1024;
        vals[t] = (i < NF) ? __float_as_uint(g_sig[b * NF + i]) : 0u;
    }
    if (tid < 32) s_cnt[tid] = 0;
    if (tid == 0) s_n = 0;
    // init candidate slots (so rank pass can read all of them safely)
    cand[tid] = 0ull;
    cand[tid + 1024] = 0ull;
    __syncthreads();

    // binary search: max thr with count(bits >= thr) >= NKEY.
    // all threads track identical lo/hi in registers -> no broadcasts.
    unsigned lo = 0u, hi = 0x3F800000u;
    #pragma unroll 1
    for (int it = 0; it < 31; ++it) {
        unsigned mid = lo + ((hi - lo) >> 1);
        int c = 0;
        #pragma unroll
        for (int t = 0; t < VPT; ++t) c += (vals[t] >= mid) ? 1 : 0;
        #pragma unroll
        for (int o = 16; o; o >>= 1) c += __shfl_xor_sync(0xffffffffu, c, o);
        if (lane == 0 && c) atomicAdd(&s_cnt[it], c);
        __syncthreads();
        if (s_cnt[it] >= NKEY) lo = mid; else hi = mid;
    }
    const unsigned thr = lo;

    // collect candidates >= thr as packed keys (value desc, tie -> lower idx)
    #pragma unroll
    for (int t = 0; t < VPT; ++t) {
        unsigned v = vals[t];
        if (v >= thr) {
            int i = tid + t * 1024;
            int p = atomicAdd(&s_n, 1);
            if (p < CANDMAX)
                cand[p] = ((unsigned long long)v << 32) |
                          (unsigned long long)(0xFFFFFFFFu - (unsigned)i);
        }
    }
    __syncthreads();
    int n = s_n; if (n > CANDMAX) n = CANDMAX;

    // rank-by-count: keys are unique (idx embedded), rank = #{j : cand[j] > mine}
    for (int s = tid; s < CANDMAX; s += 1024) {
        unsigned long long mine = cand[s];
        if (mine == 0ull || s >= n) continue;
        int rank = 0;
        for (int j = 0; j < n; ++j) rank += (cand[j] > mine) ? 1 : 0;
        if (rank < NKEY) {
            unsigned idx = 0xFFFFFFFFu - (unsigned)(mine & 0xFFFFFFFFull);
            g_topk[b * NKEY + rank] = (int)idx;
            int2 cc = ((const int2*)fusion_coords)[b * NF + (int)idx];
            int o = (b * NKEY + rank) * 3;
            outF[KVI_OFF + o + 0] = (float)b;
            outF[KVI_OFF + o + 1] = (float)cc.x;
            outF[KVI_OFF + o + 2] = (float)cc.y;
            g_keyworld[b * NKEY + rank] = make_float2(worldc(cc.x, 8.0f), worldc(cc.y, 8.0f));
            outF[KC_OFF + b * NKEY + rank] = (float)g_cls[b * NF + (int)idx];
        }
    }
}

// ---------------- K4: binned radius-KNN top-16 + neighbor-weight reduction ----
// All register-list indices are STATIC (insert network + shift-based merge) so
// the 16-entry list lives entirely in registers (no local-memory spill).
__global__ void __launch_bounds__(256) knn_kernel(
    const float* __restrict__ fa, const float* __restrict__ fb,
    const float* __restrict__ knn_w, const float* __restrict__ knn_b)
{
    const int b = blockIdx.y, src = blockIdx.z;
    const int warpId = threadIdx.x >> 5, lane = threadIdx.x & 31;
    const int key = blockIdx.x * 8 + warpId;
    if (key >= NKEY) return;
    float2 kw = g_keyworld[b * NKEY + key];
    const float kx = kw.x, ky = kw.y;
    // radius^2 computed in double by python then compared in f32 by jnp
    const float r2 = (src == 0) ? 5.76f : 23.04f;
    const float cell = (src == 0) ? CELL0 : CELL1;
    const int dim = (src == 0) ? DIM0 : DIM1;
    int cx = min(dim - 1, max(0, (int)floorf((kx + 54.0f) / cell)));
    int cy = min(dim - 1, max(0, (int)floorf((ky + 54.0f) / cell)));

    const int* ccnt = g_cellcnt[src][b];
    const float4* cpts = g_cellpts[src][b];

    // preload the 9 ring-cell (cid, count) pairs up front (independent loads)
    int cids[9];
    int cnts[9];
    int ncell = 0;
    #pragma unroll
    for (int dy = -1; dy <= 1; ++dy) {
        int yy = cy + dy;
        if (yy < 0 || yy >= dim) continue;
        #pragma unroll
        for (int dx = -1; dx <= 1; ++dx) {
            int xx = cx + dx;
            if (xx < 0 || xx >= dim) continue;
            int cid = yy * dim + xx;
            cids[ncell] = cid;
            cnts[ncell] = min(ccnt[cid], CAP);
            ++ncell;
        }
    }

    unsigned long long lst[16];
    #pragma unroll
    for (int q = 0; q < 16; ++q) lst[q] = SENT;

    for (int cc = 0; cc < ncell; ++cc) {
        const int e = cnts[cc];
        const float4* cp = cpts + cids[cc] * CAP;
        for (int i = lane; i < e; i += 32) {
            float4 p = cp[i];
            float ddx = kx - p.x;
            float ddy = ky - p.y;
            float d2 = __fadd_rn(__fmul_rn(ddx, ddx), __fmul_rn(ddy, ddy));
            if (d2 <= r2) {
                unsigned long long kk =
                    ((unsigned long long)__float_as_uint(d2) << 32) |
                    (unsigned long long)__float_as_uint(p.z);
                if (kk < lst[15]) {
                    unsigned long long cur = kk;
                    #pragma unroll
                    for (int q = 0; q < 16; ++q) {
                        unsigned long long mn = lst[q] < cur ? lst[q] : cur;
                        cur = lst[q] < cur ? cur : lst[q];
                        lst[q] = mn;
                    }
                }
            }
        }
    }

    // warp merge + immediate gather: extract the 16 globally-smallest keys.
    // winner lane shifts its list down (static indices -> stays in registers).
    const float* feat = ((src == 0) ? fa : fb) + (size_t)b * NS * C;
    float4 acc = make_float4(0.f, 0.f, 0.f, 0.f);
    for (int r = 0; r < 16; ++r) {
        unsigned long long mine = lst[0];
        unsigned long long best = mine;
        #pragma unroll
        for (int o = 16; o; o >>= 1) {
            unsigned long long other = __shfl_xor_sync(0xffffffffu, best, o);
            best = other < best ? other : best;
        }
        if (best == SENT) break;
        unsigned msk = __ballot_sync(0xffffffffu, mine == best);
        if (lane == __ffs((int)msk) - 1) {
            #pragma unroll
            for (int q = 0; q < 15; ++q) lst[q] = lst[q + 1];
            lst[15] = SENT;
        }
        unsigned idx = (unsigned)(best & 0xFFFFFFFFull);
        float4 v = *(const float4*)(feat + (size_t)idx * C + lane * 4);
        float w = knn_w[src * 16 + r];
        acc.x += w * v.x; acc.y += w * v.y; acc.z += w * v.z; acc.w += w * v.w;
    }
    float bb = knn_b[src];
    float* dst = (src == 0 ? g_mf0 : g_mf1) + (size_t)(b * NKEY + key) * C + lane * 4;
    dst[0] = acc.x + bb; dst[1] = acc.y + bb; dst[2] = acc.z + bb; dst[3] = acc.w + bb;
}

// ---------------- K5: kw MLP + softmax fusion + fuse MLP (+ cell-count reset) ----------------
__global__ void __launch_bounds__(256) fuse_kernel(
    const float* __restrict__ fusion_feat,
    const float* __restrict__ kw1, const float* __restrict__ kg1,
    const float* __restrict__ kb1, const float* __restrict__ kw2,
    const float* __restrict__ kb2,
    const float* __restrict__ fw1, const float* __restrict__ fg1,
    const float* __restrict__ fb1, const float* __restrict__ fw2,
    const float* __restrict__ fb2, float* __restrict__ outF)
{
    __shared__ float kf[8][128];
    __shared__ float h64[8][64];
    __shared__ float logit[8][3];
    __shared__ float sw[8][3];
    __shared__ float fused[8][256];
    __shared__ float h256[8][256];
    const int tid = threadIdx.x;
    const int g0 = blockIdx.x * 8;

    // reset bin counts for the next kernel_launch call (knn is stream-ordered
    // before this kernel, so all reads of g_cellcnt are complete).
    {
        int z = blockIdx.x * 256 + tid;
        if (z < 2 * B * NCELLMAX) ((int*)g_cellcnt)[z] = 0;
    }

    for (int t = tid; t < 8 * 128; t += 256) {
        int k = t >> 7, c = t & 127;
        int g = g0 + k;
        int b = g / NKEY;
        int ki = g_topk[g];
        kf[k][c] = fusion_feat[((size_t)b * NF + ki) * C + c];
    }
    __syncthreads();
    for (int t = tid; t < 512; t += 256) {
        int k = t >> 6, j = t & 63;
        float a = 0.f;
        for (int i = 0; i < 128; ++i) a += kf[k][i] * kw1[i * 64 + j];
        a = a * kg1[j] + kb1[j];
        h64[k][j] = a > 0.f ? a : 0.f;
    }
    __syncthreads();
    if (tid < 24) {
        int k = tid / 3, j = tid - k * 3;
        float a = 0.f;
        for (int i = 0; i < 64; ++i) a += h64[k][i] * kw2[i * 3 + j];
        logit[k][j] = a + kb2[j];
    }
    __syncthreads();
    if (tid < 8) {
        float l0 = logit[tid][0], l1 = logit[tid][1], l2 = logit[tid][2];
        float m = fmaxf(l0, fmaxf(l1, l2));
        float e0 = expf(l0 - m), e1 = expf(l1 - m), e2 = expf(l2 - m);
        float s = e0 + e1 + e2;
        sw[tid][0] = e0 / s; sw[tid][1] = e1 / s; sw[tid][2] = e2 / s;
    }
    __syncthreads();
    for (int t = tid; t < 1024; t += 256) {
        int k = t >> 7, c = t & 127;
        int g = g0 + k;
        float x = kf[k][c];
        float kv = sw[k][0] * x;
        float fs = kv * g_mf0[(size_t)g * C + c];
        kv = sw[k][1] * kv;
        fs += kv * g_mf1[(size_t)g * C + c];
        fused[k][c] = fs;
        fused[k][128 + c] = kv;
    }
    __syncthreads();
    {
        float acc[8];
        #pragma unroll
        for (int k = 0; k < 8; ++k) acc[k] = 0.f;
        for (int i = 0; i < 256; ++i) {
            float wv = fw1[i * 256 + tid];
            #pragma unroll
            for (int k = 0; k < 8; ++k) acc[k] += fused[k][i] * wv;
        }
        float gg = fg1[tid], bb = fb1[tid];
        #pragma unroll
        for (int k = 0; k < 8; ++k) {
            float h = acc[k] * gg + bb;
            h256[k][tid] = h > 0.f ? h : 0.f;
        }
    }
    __syncthreads();
    for (int t = tid; t < 1024; t += 256) {
        int k = t >> 7, c = t & 127;
        int g = g0 + k;
        float a = 0.f;
        for (int i = 0; i < 256; ++i) a += h256[k][i] * fw2[i * 128 + c];
        outF[OUT_OFF + (size_t)g * 128 + c] = a + fb2[c];
    }
}

// ---------------- launch ----------------
extern "C" void kernel_launch(void* const* d_in, const int* in_sizes, int n_in,
                              void* d_out, int out_size)
{
    const float* fusion_feat = (const float*)d_in[0];
    const float* src_feat_a  = (const float*)d_in[1];
    const float* src_feat_b  = (const float*)d_in[2];
    const float* heat_w1 = (const float*)d_in[3];
    const float* heat_g1 = (const float*)d_in[4];
    const float* heat_b1 = (const float*)d_in[5];
    const float* heat_w2 = (const float*)d_in[6];
    const float* heat_b2 = (const float*)d_in[7];
    const float* knn_w = (const float*)d_in[8];
    const float* knn_b = (const float*)d_in[9];
    const float* kw_w1 = (const float*)d_in[10];
    const float* kw_g1 = (const float*)d_in[11];
    const float* kw_b1 = (const float*)d_in[12];
    const float* kw_w2 = (const float*)d_in[13];
    const float* kw_b2 = (const float*)d_in[14];
    const float* fuse_w1 = (const float*)d_in[15];
    const float* fuse_g1 = (const float*)d_in[16];
    const float* fuse_b1 = (const float*)d_in[17];
    const float* fuse_w2 = (const float*)d_in[18];
    const float* fuse_b2 = (const float*)d_in[19];
    const int* fusion_coords = (const int*)d_in[20];
    const int* src_coords_a  = (const int*)d_in[21];
    const int* src_coords_b  = (const int*)d_in[22];
    float* outF = (float*)d_out;

    cudaFuncSetAttribute(heat_kernel, cudaFuncAttributeMaxDynamicSharedMemorySize, HEAT_SMEM);
    cudaFuncSetAttribute(topk_kernel, cudaFuncAttributeMaxDynamicSharedMemorySize, TOPK_SMEM);

    bin_build_kernel<<<(2 * B * NS + 255) / 256, 256>>>(src_coords_a, src_coords_b);
    heat_kernel<<<NROWS / 64, 256, HEAT_SMEM>>>(fusion_feat, heat_w1, heat_g1,
                                                heat_b1, heat_w2, heat_b2, outF);
    topk_kernel<<<B, 1024, TOPK_SMEM>>>(fusion_coords, outF);
    dim3 kg((NKEY + 7) / 8, B, 2);
    knn_kernel<<<kg, 256>>>(src_feat_a, src_feat_b, knn_w, knn_b);
    fuse_kernel<<<(B * NKEY) / 8, 256>>>(fusion_feat, kw_w1, kw_g1, kw_b1, kw_w2,
                                         kw_b2, fuse_w1, fuse_g1, fuse_b1,
                                         fuse_w2, fuse_b2, outF);
}

// round 9
// speedup vs baseline: 1.0250x; 1.0250x over previous
#include <cuda_runtime.h>
#include <math.h>

#define B 2
#define NF 20000
#define NS 30000
#define C 128
#define NKEY 500
#define NROWS (B*NF)

// output layout (flattened, float32, in reference return order)
#define OUT_OFF  0        // (1000,128)
#define KVI_OFF  128000   // (1000,3)
#define HEAT_OFF 131000   // (40000,)
#define S10_OFF  171000   // (40000,10)
#define KC_OFF   571000   // (1000,)

// spatial binning params (cell > radius with wide margin -> 3x3 ring suffices)
#define DIM0 36
#define CELL0 3.0f
#define DIM1 22
#define CELL1 5.0f
#define NCELLMAX (DIM0*DIM0)   // 1296
#define CAP 192                // fixed per-cell capacity (avg 23 / 62; huge margin)

#define SENT 0xFFFFFFFFFFFFFFFFull
#define INVIDX 0xFFFFFFFFu

// ---------------- scratch (device globals; no allocs allowed) ----------------
// NOTE: g_cellcnt must be zero at entry of every kernel_launch call. Device
// globals are zero-initialized at load, and fuse_kernel (the last kernel in
// the stream, ordered after knn's final read) re-zeroes it each call.
__device__ float g_sig[NROWS];
__device__ int   g_cls[NROWS];
__device__ int   g_topk[B*NKEY];
__device__ float2 g_keyworld[B*NKEY];
__device__ float g_mf0[B*NKEY*C];
__device__ float g_mf1[B*NKEY*C];
__device__ int    g_cellcnt[2][B][NCELLMAX];
__device__ float4 g_cellpts[2][B][NCELLMAX*CAP];   // {wx, wy, idx-bits, 0}

__device__ __forceinline__ float worldc(int c, float stride) {
    // ((c + 0.5) * stride) * 0.075 + (-54), each op fp32-rounded, no contraction
    float t = __fadd_rn((float)c, 0.5f);
    t = __fmul_rn(t, stride);
    t = __fmul_rn(t, 0.075f);
    return __fadd_rn(t, -54.0f);
}

// ---------------- K1: heat MLP (40000 x 128 -> 128 relu -> 10) ----------------
// X tile in shared; W1 streamed from L2 (hot, 64KB) -> high occupancy.
// Prologue: spatial-bin build for the KNN stage (192 points per block),
// overlapped with the GEMM latency. Bins are consumed 2 kernels later.
#define SXS 132   // padded row stride for shared X/H
#define HEAT_SMEM ((64*SXS + 128*12 + 64*10) * 4)
#define BIN_PER_BLOCK 192   // 625 blocks * 192 = 120000 = 2*B*NS exactly

__global__ void __launch_bounds__(256) heat_kernel(
    const float* __restrict__ X, const float* __restrict__ W1,
    const float* __restrict__ G1, const float* __restrict__ B1,
    const float* __restrict__ W2, const float* __restrict__ B2v,
    const int* __restrict__ ca, const int* __restrict__ cb,
    float* __restrict__ outF)
{
    extern __shared__ float sm[];
    float* sX  = sm;                     // 64 * SXS
    float* sW2 = sm + 64 * SXS;          // 128 * 12 (padded, cols>=10 zero)
    float* sS  = sW2 + 128 * 12;         // 64 * 10
    const int tid = threadIdx.x;
    const int rowbase = blockIdx.x * 64;

    // ---- bin-build prologue (independent of the MLP work) ----
    if (tid < BIN_PER_BLOCK) {
        int id = blockIdx.x * BIN_PER_BLOCK + tid;
        int src = id / (B * NS);
        int rem = id - src * (B * NS);
        int b = rem / NS, i = rem - b * NS;
        int2 cc = ((const int2*)(src == 0 ? ca : cb))[b * NS + i];
        float stride = (src == 0) ? 4.0f : 8.0f;
        float wx = worldc(cc.x, stride), wy = worldc(cc.y, stride);
        float cell = (src == 0) ? CELL0 : CELL1;
        int dim = (src == 0) ? DIM0 : DIM1;
        int cx = min(dim - 1, max(0, (int)floorf((wx + 54.0f) / cell)));
        int cy = min(dim - 1, max(0, (int)floorf((wy + 54.0f) / cell)));
        int cid = cy * dim + cx;
        int pos = atomicAdd(&g_cellcnt[src][b][cid], 1);
        if (pos < CAP)
            g_cellpts[src][b][cid * CAP + pos] =
                make_float4(wx, wy, __uint_as_float((unsigned)i), 0.f);
    }

    // load X tile (64x128) into padded shared
    {
        const float4* s = (const float4*)(X + (size_t)rowbase * C);
        #pragma unroll
        for (int t = 0; t < 8; ++t) {
            int idx = tid + t * 256;         // 0..2047 float4s
            int row = idx >> 5, c4 = idx & 31;
            *(float4*)(sX + row * SXS + c4 * 4) = s[idx];
        }
    }
    // load W2 padded to 12 cols
    for (int t = tid; t < 128 * 12; t += 256) {
        int i = t / 12, c = t - i * 12;
        sW2[t] = (c < 10) ? W2[i * 10 + c] : 0.f;
    }
    __syncthreads();

    // 16 thread-rows x 16 thread-cols; 4x8 micro-tile per thread
    const int ty = tid >> 4, tx = tid & 15;
    const int r0 = ty * 4, c0 = tx * 8;
    float acc[4][8];
    #pragma unroll
    for (int i = 0; i < 4; ++i)
        #pragma unroll
        for (int j = 0; j < 8; ++j) acc[i][j] = 0.f;

    #pragma unroll 2
    for (int k = 0; k < 128; k += 4) {
        float4 w[8];
        #pragma unroll
        for (int kk = 0; kk < 4; ++kk) {
            w[2*kk]   = __ldg((const float4*)(W1 + (k + kk) * 128 + c0));
            w[2*kk+1] = __ldg((const float4*)(W1 + (k + kk) * 128 + c0 + 4));
        }
        float4 xr[4];
        #pragma unroll
        for (int i = 0; i < 4; ++i)
            xr[i] = *(const float4*)&sX[(r0 + i) * SXS + k];
        #pragma unroll
        for (int kk = 0; kk < 4; ++kk) {
            #pragma unroll
            for (int i = 0; i < 4; ++i) {
                float x = (kk == 0) ? xr[i].x : (kk == 1) ? xr[i].y
                        : (kk == 2) ? xr[i].z : xr[i].w;
                acc[i][0] += x * w[2*kk].x;   acc[i][1] += x * w[2*kk].y;
                acc[i][2] += x * w[2*kk].z;   acc[i][3] += x * w[2*kk].w;
                acc[i][4] += x * w[2*kk+1].x; acc[i][5] += x * w[2*kk+1].y;
                acc[i][6] += x * w[2*kk+1].z; acc[i][7] += x * w[2*kk+1].w;
            }
        }
    }
    float4 ga = *(const float4*)&G1[c0], gb = *(const float4*)&G1[c0 + 4];
    float4 ba = *(const float4*)&B1[c0], bb = *(const float4*)&B1[c0 + 4];
    float gv[8] = {ga.x, ga.y, ga.z, ga.w, gb.x, gb.y, gb.z, gb.w};
    float bv[8] = {ba.x, ba.y, ba.z, ba.w, bb.x, bb.y, bb.z, bb.w};
    __syncthreads();  // all reads of sX done; safe to overwrite with H
    #pragma unroll
    for (int i = 0; i < 4; ++i)
        #pragma unroll
        for (int j = 0; j < 8; ++j) {
            float h = acc[i][j] * gv[j] + bv[j];
            sX[(r0 + i) * SXS + c0 + j] = h > 0.f ? h : 0.f;
        }
    __syncthreads();

    // stage 2: scores10 = H @ W2 + b2  (2 threads per row, 5 cols each)
    if (tid < 128) {
        const int r = tid >> 1, hhalf = tid & 1;
        const int cc0 = hhalf * 5;
        float a[5] = {0.f, 0.f, 0.f, 0.f, 0.f};
        for (int i = 0; i < 128; ++i) {
            float hv = sX[r * SXS + i];
            #pragma unroll
            for (int q = 0; q < 5; ++q) a[q] += hv * sW2[i * 12 + cc0 + q];
        }
        #pragma unroll
        for (int q = 0; q < 5; ++q) {
            int c = cc0 + q;
            float v = a[q] + B2v[c];
            outF[S10_OFF + (size_t)(rowbase + r) * 10 + c] = v;
            sS[r * 10 + c] = v;
        }
    }
    __syncthreads();
    if (tid < 64) {
        int r = tid, row = rowbase + r;
        float m = -INFINITY; int a = 0;
        #pragma unroll
        for (int c = 0; c < 10; ++c) {
            float v = sS[r * 10 + c];
            if (v > m) { m = v; a = c; }   // first max wins (jnp.argmax)
        }
        outF[HEAT_OFF + row] = m;
        g_sig[row] = 1.f / (1.f + expf(-m));
        g_cls[row] = a;
    }
}

// ---------------- K2: per-batch top-500 (jax.lax.top_k semantics) ----------------
// register-resident binary search + rank-by-count output (no bitonic sort,
// no histogram atom contention).
#define VPT 20          // values per thread: 20*1024 >= NF
#define CANDMAX 2048
#define TOPK_SMEM (CANDMAX * 8)

__global__ void __launch_bounds__(1024) topk_kernel(
    const int* __restrict__ fusion_coords, float* __restrict__ outF)
{
    extern __shared__ unsigned char dsm[];
    unsigned long long* cand = (unsigned long long*)dsm;   // CANDMAX
    __shared__ int s_cnt[32];   // one counter per binary-search iteration
    __shared__ int s_n;
    const int tid = threadIdx.x;
    const int lane = tid & 31;
    const int b = blockIdx.x;

    // load scores into registers
    unsigned vals[VPT];
    #pragma unroll
    for (int t = 0; t < VPT; ++t) {
        int i = tid + t * 1024;
        vals[t] = (i < NF) ? __float_as_uint(g_sig[b * NF + i]) : 0u;
    }
    if (tid < 32) s_cnt[tid] = 0;
    if (tid == 0) s_n = 0;
    // init candidate slots (so rank pass can read all of them safely)
    cand[tid] = 0ull;
    cand[tid + 1024] = 0ull;
    __syncthreads();

    // binary search: max thr with count(bits >= thr) >= NKEY.
    // all threads track identical lo/hi in registers -> no broadcasts.
    unsigned lo = 0u, hi = 0x3F800000u;
    #pragma unroll 1
    for (int it = 0; it < 31; ++it) {
        unsigned mid = lo + ((hi - lo) >> 1);
        int c = 0;
        #pragma unroll
        for (int t = 0; t < VPT; ++t) c += (vals[t] >= mid) ? 1 : 0;
        #pragma unroll
        for (int o = 16; o; o >>= 1) c += __shfl_xor_sync(0xffffffffu, c, o);
        if (lane == 0 && c) atomicAdd(&s_cnt[it], c);
        __syncthreads();
        if (s_cnt[it] >= NKEY) lo = mid; else hi = mid;
    }
    const unsigned thr = lo;

    // collect candidates >= thr as packed keys (value desc, tie -> lower idx)
    #pragma unroll
    for (int t = 0; t < VPT; ++t) {
        unsigned v = vals[t];
        if (v >= thr) {
            int i = tid + t * 1024;
            int p = atomicAdd(&s_n, 1);
            if (p < CANDMAX)
                cand[p] = ((unsigned long long)v << 32) |
                          (unsigned long long)(0xFFFFFFFFu - (unsigned)i);
        }
    }
    __syncthreads();
    int n = s_n; if (n > CANDMAX) n = CANDMAX;

    // rank-by-count: keys are unique (idx embedded), rank = #{j : cand[j] > mine}
    for (int s = tid; s < CANDMAX; s += 1024) {
        unsigned long long mine = cand[s];
        if (mine == 0ull || s >= n) continue;
        int rank = 0;
        for (int j = 0; j < n; ++j) rank += (cand[j] > mine) ? 1 : 0;
        if (rank < NKEY) {
            unsigned idx = 0xFFFFFFFFu - (unsigned)(mine & 0xFFFFFFFFull);
            g_topk[b * NKEY + rank] = (int)idx;
            int2 cc = ((const int2*)fusion_coords)[b * NF + (int)idx];
            int o = (b * NKEY + rank) * 3;
            outF[KVI_OFF + o + 0] = (float)b;
            outF[KVI_OFF + o + 1] = (float)cc.x;
            outF[KVI_OFF + o + 2] = (float)cc.y;
            g_keyworld[b * NKEY + rank] = make_float2(worldc(cc.x, 8.0f), worldc(cc.y, 8.0f));
            outF[KC_OFF + b * NKEY + rank] = (float)g_cls[b * NF + (int)idx];
        }
    }
}

// ---------------- K4: binned radius-KNN top-16 + neighbor-weight reduction ----
// Selection (merge) is fully unrolled into static registers, THEN all 16
// feature-row loads issue as one independent batch (MLP=16, hides DRAM latency).
__global__ void __launch_bounds__(256) knn_kernel(
    const float* __restrict__ fa, const float* __restrict__ fb,
    const float* __restrict__ knn_w, const float* __restrict__ knn_b)
{
    const int b = blockIdx.y, src = blockIdx.z;
    const int warpId = threadIdx.x >> 5, lane = threadIdx.x & 31;
    const int key = blockIdx.x * 8 + warpId;
    if (key >= NKEY) return;
    float2 kw = g_keyworld[b * NKEY + key];
    const float kx = kw.x, ky = kw.y;
    // radius^2 computed in double by python then compared in f32 by jnp
    const float r2 = (src == 0) ? 5.76f : 23.04f;
    const float cell = (src == 0) ? CELL0 : CELL1;
    const int dim = (src == 0) ? DIM0 : DIM1;
    int cx = min(dim - 1, max(0, (int)floorf((kx + 54.0f) / cell)));
    int cy = min(dim - 1, max(0, (int)floorf((ky + 54.0f) / cell)));

    const int* ccnt = g_cellcnt[src][b];
    const float4* cpts = g_cellpts[src][b];

    // preload the 9 ring-cell (cid, count) pairs up front (independent loads)
    int cids[9];
    int cnts[9];
    int ncell = 0;
    #pragma unroll
    for (int dy = -1; dy <= 1; ++dy) {
        int yy = cy + dy;
        if (yy < 0 || yy >= dim) continue;
        #pragma unroll
        for (int dx = -1; dx <= 1; ++dx) {
            int xx = cx + dx;
            if (xx < 0 || xx >= dim) continue;
            int cid = yy * dim + xx;
            cids[ncell] = cid;
            cnts[ncell] = min(ccnt[cid], CAP);
            ++ncell;
        }
    }

    unsigned long long lst[16];
    #pragma unroll
    for (int q = 0; q < 16; ++q) lst[q] = SENT;

    for (int cc = 0; cc < ncell; ++cc) {
        const int e = cnts[cc];
        const float4* cp = cpts + cids[cc] * CAP;
        for (int i = lane; i < e; i += 32) {
            float4 p = cp[i];
            float ddx = kx - p.x;
            float ddy = ky - p.y;
            float d2 = __fadd_rn(__fmul_rn(ddx, ddx), __fmul_rn(ddy, ddy));
            if (d2 <= r2) {
                unsigned long long kk =
                    ((unsigned long long)__float_as_uint(d2) << 32) |
                    (unsigned long long)__float_as_uint(p.z);
                if (kk < lst[15]) {
                    unsigned long long cur = kk;
                    #pragma unroll
                    for (int q = 0; q < 16; ++q) {
                        unsigned long long mn = lst[q] < cur ? lst[q] : cur;
                        cur = lst[q] < cur ? cur : lst[q];
                        lst[q] = mn;
                    }
                }
            }
        }
    }

    // Phase 1: warp merge — extract the 16 globally-smallest keys into
    // statically-indexed registers (fully unrolled; no loads inside).
    unsigned nIdx[16];
    #pragma unroll
    for (int r = 0; r < 16; ++r) {
        unsigned long long mine = lst[0];
        unsigned long long best = mine;
        #pragma unroll
        for (int o = 16; o; o >>= 1) {
            unsigned long long other = __shfl_xor_sync(0xffffffffu, best, o);
            best = other < best ? other : best;
        }
        unsigned msk = __ballot_sync(0xffffffffu, mine == best);
        if (lane == __ffs((int)msk) - 1) {
            #pragma unroll
            for (int q = 0; q < 15; ++q) lst[q] = lst[q + 1];
            lst[15] = SENT;
        }
        nIdx[r] = (best == SENT) ? INVIDX : (unsigned)(best & 0xFFFFFFFFull);
    }

    // Phase 2: batched gather — 16 independent row loads in flight at once.
    const float* feat = ((src == 0) ? fa : fb) + (size_t)b * NS * C;
    float4 acc = make_float4(0.f, 0.f, 0.f, 0.f);
    #pragma unroll
    for (int r = 0; r < 16; ++r) {
        unsigned idx = nIdx[r];
        unsigned safe = (idx == INVIDX) ? 0u : idx;
        float w = (idx == INVIDX) ? 0.f : __ldg(&knn_w[src * 16 + r]);
        float4 v = *(const float4*)(feat + (size_t)safe * C + lane * 4);
        acc.x += w * v.x; acc.y += w * v.y; acc.z += w * v.z; acc.w += w * v.w;
    }
    float bb = knn_b[src];
    float* dst = (src == 0 ? g_mf0 : g_mf1) + (size_t)(b * NKEY + key) * C + lane * 4;
    dst[0] = acc.x + bb; dst[1] = acc.y + bb; dst[2] = acc.z + bb; dst[3] = acc.w + bb;
}

// ---------------- K5: kw MLP + softmax fusion + fuse MLP (+ cell-count reset) ----------------
__global__ void __launch_bounds__(256) fuse_kernel(
    const float* __restrict__ fusion_feat,
    const float* __restrict__ kw1, const float* __restrict__ kg1,
    const float* __restrict__ kb1, const float* __restrict__ kw2,
    const float* __restrict__ kb2,
    const float* __restrict__ fw1, const float* __restrict__ fg1,
    const float* __restrict__ fb1, const float* __restrict__ fw2,
    const float* __restrict__ fb2, float* __restrict__ outF)
{
    __shared__ float kf[8][128];
    __shared__ float h64[8][64];
    __shared__ float logit[8][3];
    __shared__ float sw[8][3];
    __shared__ float fused[8][256];
    __shared__ float h256[8][256];
    const int tid = threadIdx.x;
    const int g0 = blockIdx.x * 8;

    // reset bin counts for the next kernel_launch call (knn is stream-ordered
    // before this kernel, so all reads of g_cellcnt are complete).
    {
        int z = blockIdx.x * 256 + tid;
        if (z < 2 * B * NCELLMAX) ((int*)g_cellcnt)[z] = 0;
    }

    for (int t = tid; t < 8 * 128; t += 256) {
        int k = t >> 7, c = t & 127;
        int g = g0 + k;
        int b = g / NKEY;
        int ki = g_topk[g];
        kf[k][c] = fusion_feat[((size_t)b * NF + ki) * C + c];
    }
    __syncthreads();
    for (int t = tid; t < 512; t += 256) {
        int k = t >> 6, j = t & 63;
        float a = 0.f;
        for (int i = 0; i < 128; ++i) a += kf[k][i] * kw1[i * 64 + j];
        a = a * kg1[j] + kb1[j];
        h64[k][j] = a > 0.f ? a : 0.f;
    }
    __syncthreads();
    if (tid < 24) {
        int k = tid / 3, j = tid - k * 3;
        float a = 0.f;
        for (int i = 0; i < 64; ++i) a += h64[k][i] * kw2[i * 3 + j];
        logit[k][j] = a + kb2[j];
    }
    __syncthreads();
    if (tid < 8) {
        float l0 = logit[tid][0], l1 = logit[tid][1], l2 = logit[tid][2];
        float m = fmaxf(l0, fmaxf(l1, l2));
        float e0 = expf(l0 - m), e1 = expf(l1 - m), e2 = expf(l2 - m);
        float s = e0 + e1 + e2;
        sw[tid][0] = e0 / s; sw[tid][1] = e1 / s; sw[tid][2] = e2 / s;
    }
    __syncthreads();
    for (int t = tid; t < 1024; t += 256) {
        int k = t >> 7, c = t & 127;
        int g = g0 + k;
        float x = kf[k][c];
        float kv = sw[k][0] * x;
        float fs = kv * g_mf0[(size_t)g * C + c];
        kv = sw[k][1] * kv;
        fs += kv * g_mf1[(size_t)g * C + c];
        fused[k][c] = fs;
        fused[k][128 + c] = kv;
    }
    __syncthreads();
    {
        float acc[8];
        #pragma unroll
        for (int k = 0; k < 8; ++k) acc[k] = 0.f;
        for (int i = 0; i < 256; ++i) {
            float wv = fw1[i * 256 + tid];
            #pragma unroll
            for (int k = 0; k < 8; ++k) acc[k] += fused[k][i] * wv;
        }
        float gg = fg1[tid], bb = fb1[tid];
        #pragma unroll
        for (int k = 0; k < 8; ++k) {
            float h = acc[k] * gg + bb;
            h256[k][tid] = h > 0.f ? h : 0.f;
        }
    }
    __syncthreads();
    for (int t = tid; t < 1024; t += 256) {
        int k = t >> 7, c = t & 127;
        int g = g0 + k;
        float a = 0.f;
        for (int i = 0; i < 256; ++i) a += h256[k][i] * fw2[i * 128 + c];
        outF[OUT_OFF + (size_t)g * 128 + c] = a + fb2[c];
    }
}

// ---------------- launch ----------------
extern "C" void kernel_launch(void* const* d_in, const int* in_sizes, int n_in,
                              void* d_out, int out_size)
{
    const float* fusion_feat = (const float*)d_in[0];
    const float* src_feat_a  = (const float*)d_in[1];
    const float* src_feat_b  = (const float*)d_in[2];
    const float* heat_w1 = (const float*)d_in[3];
    const float* heat_g1 = (const float*)d_in[4];
    const float* heat_b1 = (const float*)d_in[5];
    const float* heat_w2 = (const float*)d_in[6];
    const float* heat_b2 = (const float*)d_in[7];
    const float* knn_w = (const float*)d_in[8];
    const float* knn_b = (const float*)d_in[9];
    const float* kw_w1 = (const float*)d_in[10];
    const float* kw_g1 = (const float*)d_in[11];
    const float* kw_b1 = (const float*)d_in[12];
    const float* kw_w2 = (const float*)d_in[13];
    const float* kw_b2 = (const float*)d_in[14];
    const float* fuse_w1 = (const float*)d_in[15];
    const float* fuse_g1 = (const float*)d_in[16];
    const float* fuse_b1 = (const float*)d_in[17];
    const float* fuse_w2 = (const float*)d_in[18];
    const float* fuse_b2 = (const float*)d_in[19];
    const int* fusion_coords = (const int*)d_in[20];
    const int* src_coords_a  = (const int*)d_in[21];
    const int* src_coords_b  = (const int*)d_in[22];
    float* outF = (float*)d_out;

    cudaFuncSetAttribute(heat_kernel, cudaFuncAttributeMaxDynamicSharedMemorySize, HEAT_SMEM);
    cudaFuncSetAttribute(topk_kernel, cudaFuncAttributeMaxDynamicSharedMemorySize, TOPK_SMEM);

    heat_kernel<<<NROWS / 64, 256, HEAT_SMEM>>>(fusion_feat, heat_w1, heat_g1,
                                                heat_b1, heat_w2, heat_b2,
                                                src_coords_a, src_coords_b, outF);
    topk_kernel<<<B, 1024, TOPK_SMEM>>>(fusion_coords, outF);
    dim3 kg((NKEY + 7) / 8, B, 2);
    knn_kernel<<<kg, 256>>>(src_feat_a, src_feat_b, knn_w, knn_b);
    fuse_kernel<<<(B * NKEY) / 8, 256>>>(fusion_feat, kw_w1, kw_g1, kw_b1, kw_w2,
                                         kw_b2, fuse_w1, fuse_g1, fuse_b1,
                                         fuse_w2, fuse_b2, outF);
}

// round 10
// speedup vs baseline: 1.0510x; 1.0253x over previous
#include <cuda_runtime.h>
#include <math.h>

#define B 2
#define NF 20000
#define NS 30000
#define C 128
#define NKEY 500
#define NROWS (B*NF)
#define NK_TOT (B*NKEY)   // 1000

// output layout (flattened, float32, in reference return order)
#define OUT_OFF  0        // (1000,128)
#define KVI_OFF  128000   // (1000,3)
#define HEAT_OFF 131000   // (40000,)
#define S10_OFF  171000   // (40000,10)
#define KC_OFF   571000   // (1000,)

// spatial binning params (cell > radius with wide margin -> 3x3 ring suffices)
#define DIM0 36
#define CELL0 3.0f
#define DIM1 22
#define CELL1 5.0f
#define NCELLMAX (DIM0*DIM0)   // 1296
#define CAP 192                // fixed per-cell capacity (avg 23 / 62; huge margin)

#define SENT 0xFFFFFFFFFFFFFFFFull
#define INVIDX 0xFFFFFFFFu

// ---------------- scratch (device globals; no allocs allowed) ----------------
// NOTE: g_cellcnt must be zero at entry of every kernel_launch call. Device
// globals are zero-initialized at load, and fuse_prep (stream-ordered after
// knn's final read) re-zeroes it each call.
__device__ float g_sig[NROWS];
__device__ int   g_cls[NROWS];
__device__ int   g_topk[NK_TOT];
__device__ float2 g_keyworld[NK_TOT];
__device__ float g_mf0[NK_TOT*C];
__device__ float g_mf1[NK_TOT*C];
__device__ float g_fused[NK_TOT*256];
__device__ float g_h[NK_TOT*256];
__device__ int    g_cellcnt[2][B][NCELLMAX];
__device__ float4 g_cellpts[2][B][NCELLMAX*CAP];   // {wx, wy, idx-bits, 0}

__device__ __forceinline__ float worldc(int c, float stride) {
    // ((c + 0.5) * stride) * 0.075 + (-54), each op fp32-rounded, no contraction
    float t = __fadd_rn((float)c, 0.5f);
    t = __fmul_rn(t, stride);
    t = __fmul_rn(t, 0.075f);
    return __fadd_rn(t, -54.0f);
}

// ---------------- K1: heat MLP (40000 x 128 -> 128 relu -> 10) ----------------
// X tile in shared; W1 streamed from L2 (hot, 64KB) -> high occupancy.
// Prologue: spatial-bin build for the KNN stage (192 points per block),
// overlapped with the GEMM latency. Bins are consumed 2 kernels later.
#define SXS 132   // padded row stride for shared X/H
#define HEAT_SMEM ((64*SXS + 128*12 + 64*10) * 4)
#define BIN_PER_BLOCK 192   // 625 blocks * 192 = 120000 = 2*B*NS exactly

__global__ void __launch_bounds__(256) heat_kernel(
    const float* __restrict__ X, const float* __restrict__ W1,
    const float* __restrict__ G1, const float* __restrict__ B1,
    const float* __restrict__ W2, const float* __restrict__ B2v,
    const int* __restrict__ ca, const int* __restrict__ cb,
    float* __restrict__ outF)
{
    extern __shared__ float sm[];
    float* sX  = sm;                     // 64 * SXS
    float* sW2 = sm + 64 * SXS;          // 128 * 12 (padded, cols>=10 zero)
    float* sS  = sW2 + 128 * 12;         // 64 * 10
    const int tid = threadIdx.x;
    const int rowbase = blockIdx.x * 64;

    // ---- bin-build prologue (independent of the MLP work) ----
    if (tid < BIN_PER_BLOCK) {
        int id = blockIdx.x * BIN_PER_BLOCK + tid;
        int src = id / (B * NS);
        int rem = id - src * (B * NS);
        int b = rem / NS, i = rem - b * NS;
        int2 cc = ((const int2*)(src == 0 ? ca : cb))[b * NS + i];
        float stride = (src == 0) ? 4.0f : 8.0f;
        float wx = worldc(cc.x, stride), wy = worldc(cc.y, stride);
        float cell = (src == 0) ? CELL0 : CELL1;
        int dim = (src == 0) ? DIM0 : DIM1;
        int cx = min(dim - 1, max(0, (int)floorf((wx + 54.0f) / cell)));
        int cy = min(dim - 1, max(0, (int)floorf((wy + 54.0f) / cell)));
        int cid = cy * dim + cx;
        int pos = atomicAdd(&g_cellcnt[src][b][cid], 1);
        if (pos < CAP)
            g_cellpts[src][b][cid * CAP + pos] =
                make_float4(wx, wy, __uint_as_float((unsigned)i), 0.f);
    }

    // load X tile (64x128) into padded shared
    {
        const float4* s = (const float4*)(X + (size_t)rowbase * C);
        #pragma unroll
        for (int t = 0; t < 8; ++t) {
            int idx = tid + t * 256;         // 0..2047 float4s
            int row = idx >> 5, c4 = idx & 31;
            *(float4*)(sX + row * SXS + c4 * 4) = s[idx];
        }
    }
    // load W2 padded to 12 cols
    for (int t = tid; t < 128 * 12; t += 256) {
        int i = t / 12, c = t - i * 12;
        sW2[t] = (c < 10) ? W2[i * 10 + c] : 0.f;
    }
    __syncthreads();

    // 16 thread-rows x 16 thread-cols; 4x8 micro-tile per thread
    const int ty = tid >> 4, tx = tid & 15;
    const int r0 = ty * 4, c0 = tx * 8;
    float acc[4][8];
    #pragma unroll
    for (int i = 0; i < 4; ++i)
        #pragma unroll
        for (int j = 0; j < 8; ++j) acc[i][j] = 0.f;

    #pragma unroll 2
    for (int k = 0; k < 128; k += 4) {
        float4 w[8];
        #pragma unroll
        for (int kk = 0; kk < 4; ++kk) {
            w[2*kk]   = __ldg((const float4*)(W1 + (k + kk) * 128 + c0));
            w[2*kk+1] = __ldg((const float4*)(W1 + (k + kk) * 128 + c0 + 4));
        }
        float4 xr[4];
        #pragma unroll
        for (int i = 0; i < 4; ++i)
            xr[i] = *(const float4*)&sX[(r0 + i) * SXS + k];
        #pragma unroll
        for (int kk = 0; kk < 4; ++kk) {
            #pragma unroll
            for (int i = 0; i < 4; ++i) {
                float x = (kk == 0) ? xr[i].x : (kk == 1) ? xr[i].y
                        : (kk == 2) ? xr[i].z : xr[i].w;
                acc[i][0] += x * w[2*kk].x;   acc[i][1] += x * w[2*kk].y;
                acc[i][2] += x * w[2*kk].z;   acc[i][3] += x * w[2*kk].w;
                acc[i][4] += x * w[2*kk+1].x; acc[i][5] += x * w[2*kk+1].y;
                acc[i][6] += x * w[2*kk+1].z; acc[i][7] += x * w[2*kk+1].w;
            }
        }
    }
    float4 ga = *(const float4*)&G1[c0], gb = *(const float4*)&G1[c0 + 4];
    float4 ba = *(const float4*)&B1[c0], bb = *(const float4*)&B1[c0 + 4];
    float gv[8] = {ga.x, ga.y, ga.z, ga.w, gb.x, gb.y, gb.z, gb.w};
    float bv[8] = {ba.x, ba.y, ba.z, ba.w, bb.x, bb.y, bb.z, bb.w};
    __syncthreads();  // all reads of sX done; safe to overwrite with H
    #pragma unroll
    for (int i = 0; i < 4; ++i)
        #pragma unroll
        for (int j = 0; j < 8; ++j) {
            float h = acc[i][j] * gv[j] + bv[j];
            sX[(r0 + i) * SXS + c0 + j] = h > 0.f ? h : 0.f;
        }
    __syncthreads();

    // stage 2: scores10 = H @ W2 + b2  (2 threads per row, 5 cols each)
    if (tid < 128) {
        const int r = tid >> 1, hhalf = tid & 1;
        const int cc0 = hhalf * 5;
        float a[5] = {0.f, 0.f, 0.f, 0.f, 0.f};
        for (int i = 0; i < 128; ++i) {
            float hv = sX[r * SXS + i];
            #pragma unroll
            for (int q = 0; q < 5; ++q) a[q] += hv * sW2[i * 12 + cc0 + q];
        }
        #pragma unroll
        for (int q = 0; q < 5; ++q) {
            int c = cc0 + q;
            float v = a[q] + B2v[c];
            outF[S10_OFF + (size_t)(rowbase + r) * 10 + c] = v;
            sS[r * 10 + c] = v;
        }
    }
    __syncthreads();
    if (tid < 64) {
        int r = tid, row = rowbase + r;
        float m = -INFINITY; int a = 0;
        #pragma unroll
        for (int c = 0; c < 10; ++c) {
            float v = sS[r * 10 + c];
            if (v > m) { m = v; a = c; }   // first max wins (jnp.argmax)
        }
        outF[HEAT_OFF + row] = m;
        g_sig[row] = 1.f / (1.f + expf(-m));
        g_cls[row] = a;
    }
}

// ---------------- K2: per-batch top-500 (jax.lax.top_k semantics) ----------------
#define VPT 20          // values per thread: 20*1024 >= NF
#define CANDMAX 2048
#define TOPK_SMEM (CANDMAX * 8)

__global__ void __launch_bounds__(1024) topk_kernel(
    const int* __restrict__ fusion_coords, float* __restrict__ outF)
{
    extern __shared__ unsigned char dsm[];
    unsigned long long* cand = (unsigned long long*)dsm;   // CANDMAX
    __shared__ int s_cnt[32];   // one counter per binary-search iteration
    __shared__ int s_n;
    const int tid = threadIdx.x;
    const int lane = tid & 31;
    const int b = blockIdx.x;

    // load scores into registers
    unsigned vals[VPT];
    #pragma unroll
    for (int t = 0; t < VPT; ++t) {
        int i = tid + t * 1024;
        vals[t] = (i < NF) ? __float_as_uint(g_sig[b * NF + i]) : 0u;
    }
    if (tid < 32) s_cnt[tid] = 0;
    if (tid == 0) s_n = 0;
    cand[tid] = 0ull;
    cand[tid + 1024] = 0ull;
    __syncthreads();

    // binary search: max thr with count(bits >= thr) >= NKEY.
    unsigned lo = 0u, hi = 0x3F800000u;
    #pragma unroll 1
    for (int it = 0; it < 31; ++it) {
        unsigned mid = lo + ((hi - lo) >> 1);
        int c = 0;
        #pragma unroll
        for (int t = 0; t < VPT; ++t) c += (vals[t] >= mid) ? 1 : 0;
        #pragma unroll
        for (int o = 16; o; o >>= 1) c += __shfl_xor_sync(0xffffffffu, c, o);
        if (lane == 0 && c) atomicAdd(&s_cnt[it], c);
        __syncthreads();
        if (s_cnt[it] >= NKEY) lo = mid; else hi = mid;
    }
    const unsigned thr = lo;

    // collect candidates >= thr as packed keys (value desc, tie -> lower idx)
    #pragma unroll
    for (int t = 0; t < VPT; ++t) {
        unsigned v = vals[t];
        if (v >= thr) {
            int i = tid + t * 1024;
            int p = atomicAdd(&s_n, 1);
            if (p < CANDMAX)
                cand[p] = ((unsigned long long)v << 32) |
                          (unsigned long long)(0xFFFFFFFFu - (unsigned)i);
        }
    }
    __syncthreads();
    int n = s_n; if (n > CANDMAX) n = CANDMAX;

    // rank-by-count: keys are unique (idx embedded), rank = #{j : cand[j] > mine}
    for (int s = tid; s < CANDMAX; s += 1024) {
        unsigned long long mine = cand[s];
        if (mine == 0ull || s >= n) continue;
        int rank = 0;
        for (int j = 0; j < n; ++j) rank += (cand[j] > mine) ? 1 : 0;
        if (rank < NKEY) {
            unsigned idx = 0xFFFFFFFFu - (unsigned)(mine & 0xFFFFFFFFull);
            g_topk[b * NKEY + rank] = (int)idx;
            int2 cc = ((const int2*)fusion_coords)[b * NF + (int)idx];
            int o = (b * NKEY + rank) * 3;
            outF[KVI_OFF + o + 0] = (float)b;
            outF[KVI_OFF + o + 1] = (float)cc.x;
            outF[KVI_OFF + o + 2] = (float)cc.y;
            g_keyworld[b * NKEY + rank] = make_float2(worldc(cc.x, 8.0f), worldc(cc.y, 8.0f));
            outF[KC_OFF + b * NKEY + rank] = (float)g_cls[b * NF + (int)idx];
        }
    }
}

// ---------------- K4: binned radius-KNN top-16 + neighbor-weight reduction ----
__global__ void __launch_bounds__(256) knn_kernel(
    const float* __restrict__ fa, const float* __restrict__ fb,
    const float* __restrict__ knn_w, const float* __restrict__ knn_b)
{
    const int b = blockIdx.y, src = blockIdx.z;
    const int warpId = threadIdx.x >> 5, lane = threadIdx.x & 31;
    const int key = blockIdx.x * 8 + warpId;
    if (key >= NKEY) return;
    float2 kw = g_keyworld[b * NKEY + key];
    const float kx = kw.x, ky = kw.y;
    // radius^2 computed in double by python then compared in f32 by jnp
    const float r2 = (src == 0) ? 5.76f : 23.04f;
    const float cell = (src == 0) ? CELL0 : CELL1;
    const int dim = (src == 0) ? DIM0 : DIM1;
    int cx = min(dim - 1, max(0, (int)floorf((kx + 54.0f) / cell)));
    int cy = min(dim - 1, max(0, (int)floorf((ky + 54.0f) / cell)));

    const int* ccnt = g_cellcnt[src][b];
    const float4* cpts = g_cellpts[src][b];

    int cids[9];
    int cnts[9];
    int ncell = 0;
    #pragma unroll
    for (int dy = -1; dy <= 1; ++dy) {
        int yy = cy + dy;
        if (yy < 0 || yy >= dim) continue;
        #pragma unroll
        for (int dx = -1; dx <= 1; ++dx) {
            int xx = cx + dx;
            if (xx < 0 || xx >= dim) continue;
            int cid = yy * dim + xx;
            cids[ncell] = cid;
            cnts[ncell] = min(ccnt[cid], CAP);
            ++ncell;
        }
    }

    unsigned long long lst[16];
    #pragma unroll
    for (int q = 0; q < 16; ++q) lst[q] = SENT;

    for (int cc = 0; cc < ncell; ++cc) {
        const int e = cnts[cc];
        const float4* cp = cpts + cids[cc] * CAP;
        for (int i = lane; i < e; i += 32) {
            float4 p = cp[i];
            float ddx = kx - p.x;
            float ddy = ky - p.y;
            float d2 = __fadd_rn(__fmul_rn(ddx, ddx), __fmul_rn(ddy, ddy));
            if (d2 <= r2) {
                unsigned long long kk =
                    ((unsigned long long)__float_as_uint(d2) << 32) |
                    (unsigned long long)__float_as_uint(p.z);
                if (kk < lst[15]) {
                    unsigned long long cur = kk;
                    #pragma unroll
                    for (int q = 0; q < 16; ++q) {
                        unsigned long long mn = lst[q] < cur ? lst[q] : cur;
                        cur = lst[q] < cur ? cur : lst[q];
                        lst[q] = mn;
                    }
                }
            }
        }
    }

    // Phase 1: warp merge — extract the 16 globally-smallest keys into
    // statically-indexed registers (fully unrolled; no loads inside).
    unsigned nIdx[16];
    #pragma unroll
    for (int r = 0; r < 16; ++r) {
        unsigned long long mine = lst[0];
        unsigned long long best = mine;
        #pragma unroll
        for (int o = 16; o; o >>= 1) {
            unsigned long long other = __shfl_xor_sync(0xffffffffu, best, o);
            best = other < best ? other : best;
        }
        unsigned msk = __ballot_sync(0xffffffffu, mine == best);
        if (lane == __ffs((int)msk) - 1) {
            #pragma unroll
            for (int q = 0; q < 15; ++q) lst[q] = lst[q + 1];
            lst[15] = SENT;
        }
        nIdx[r] = (best == SENT) ? INVIDX : (unsigned)(best & 0xFFFFFFFFull);
    }

    // Phase 2: batched gather — 16 independent row loads in flight at once.
    const float* feat = ((src == 0) ? fa : fb) + (size_t)b * NS * C;
    float4 acc = make_float4(0.f, 0.f, 0.f, 0.f);
    #pragma unroll
    for (int r = 0; r < 16; ++r) {
        unsigned idx = nIdx[r];
        unsigned safe = (idx == INVIDX) ? 0u : idx;
        float w = (idx == INVIDX) ? 0.f : __ldg(&knn_w[src * 16 + r]);
        float4 v = *(const float4*)(feat + (size_t)safe * C + lane * 4);
        acc.x += w * v.x; acc.y += w * v.y; acc.z += w * v.z; acc.w += w * v.w;
    }
    float bb = knn_b[src];
    float* dst = (src == 0 ? g_mf0 : g_mf1) + (size_t)(b * NKEY + key) * C + lane * 4;
    dst[0] = acc.x + bb; dst[1] = acc.y + bb; dst[2] = acc.z + bb; dst[3] = acc.w + bb;
}

// ---------------- K5a: kw MLP + softmax + fused-vector build (+ cell reset) ----
__global__ void __launch_bounds__(256) fuse_prep_kernel(
    const float* __restrict__ fusion_feat,
    const float* __restrict__ kw1, const float* __restrict__ kg1,
    const float* __restrict__ kb1, const float* __restrict__ kw2,
    const float* __restrict__ kb2)
{
    __shared__ float kf[8][128];
    __shared__ float skw1[128 * 64];
    __shared__ float h64[8][64];
    __shared__ float logit[8][3];
    __shared__ float sw[8][3];
    const int tid = threadIdx.x;
    const int g0 = blockIdx.x * 8;

    // reset bin counts for the next kernel_launch call (knn is stream-ordered
    // before this kernel, so all reads of g_cellcnt are complete).
    {
        int z = blockIdx.x * 256 + tid;
        if (z < 2 * B * NCELLMAX) ((int*)g_cellcnt)[z] = 0;
    }

    // stage kw1 (128x64) into shared (coalesced float4)
    {
        float4* d = (float4*)skw1;
        const float4* s = (const float4*)kw1;
        #pragma unroll
        for (int t = 0; t < 8; ++t) d[tid + t * 256] = s[tid + t * 256];
    }
    for (int t = tid; t < 8 * 128; t += 256) {
        int k = t >> 7, c = t & 127;
        int g = g0 + k;
        int b = g / NKEY;
        int ki = g_topk[g];
        kf[k][c] = fusion_feat[((size_t)b * NF + ki) * C + c];
    }
    __syncthreads();
    // h64 = relu((kf @ kw1)*g1 + b1): 512 outputs, 2 per thread
    #pragma unroll
    for (int t = tid; t < 512; t += 256) {
        int k = t >> 6, j = t & 63;
        float a = 0.f;
        #pragma unroll 4
        for (int i = 0; i < 128; ++i) a += kf[k][i] * skw1[i * 64 + j];
        a = a * kg1[j] + kb1[j];
        h64[k][j] = a > 0.f ? a : 0.f;
    }
    __syncthreads();
    if (tid < 24) {
        int k = tid / 3, j = tid - k * 3;
        float a = 0.f;
        #pragma unroll 4
        for (int i = 0; i < 64; ++i) a += h64[k][i] * kw2[i * 3 + j];
        logit[k][j] = a + kb2[j];
    }
    __syncthreads();
    if (tid < 8) {
        float l0 = logit[tid][0], l1 = logit[tid][1], l2 = logit[tid][2];
        float m = fmaxf(l0, fmaxf(l1, l2));
        float e0 = expf(l0 - m), e1 = expf(l1 - m), e2 = expf(l2 - m);
        float s = e0 + e1 + e2;
        sw[tid][0] = e0 / s; sw[tid][1] = e1 / s; sw[tid][2] = e2 / s;
    }
    __syncthreads();
    // fused[g][0:128] = fuse_sum, fused[g][128:256] = kvf (after 2 scalings)
    for (int t = tid; t < 1024; t += 256) {
        int k = t >> 7, c = t & 127;
        int g = g0 + k;
        float x = kf[k][c];
        float kv = sw[k][0] * x;
        float fs = kv * g_mf0[(size_t)g * C + c];
        kv = sw[k][1] * kv;
        fs += kv * g_mf1[(size_t)g * C + c];
        g_fused[(size_t)g * 256 + c] = fs;
        g_fused[(size_t)g * 256 + 128 + c] = kv;
    }
}

// ---------------- K5b: H = relu((fused @ fw1)*g + b)  [1000x256 @ 256x256] ----
// grid (63, 4): 16 rows x 64 cols per block, 256 threads (4 row-groups x 64 cols)
__global__ void __launch_bounds__(256) fuse_mlp1_kernel(
    const float* __restrict__ fw1, const float* __restrict__ fg1,
    const float* __restrict__ fb1)
{
    __shared__ float sF[16][260];
    const int tid = threadIdx.x;
    const int rb = blockIdx.x * 16;
    const int cb = blockIdx.y * 64;

    // load 16 rows x 256 cols (zero-pad rows >= NK_TOT)
    #pragma unroll
    for (int t = 0; t < 4; ++t) {
        int idx = tid + t * 256;        // 0..1023 float4s
        int row = idx >> 6, c4 = idx & 63;
        int gr = rb + row;
        float4 v = make_float4(0.f, 0.f, 0.f, 0.f);
        if (gr < NK_TOT) v = *(const float4*)&g_fused[(size_t)gr * 256 + c4 * 4];
        *(float4*)&sF[row][c4 * 4] = v;
    }
    __syncthreads();

    const int cg = tid & 63, rg = tid >> 6;    // col thread, row group
    const int c = cb + cg;
    float acc[4] = {0.f, 0.f, 0.f, 0.f};
    #pragma unroll 4
    for (int i = 0; i < 256; ++i) {
        float w = __ldg(&fw1[i * 256 + c]);
        #pragma unroll
        for (int r = 0; r < 4; ++r) acc[r] += sF[rg * 4 + r][i] * w;
    }
    const float gg = fg1[c], bb = fb1[c];
    #pragma unroll
    for (int r = 0; r < 4; ++r) {
        int gr = rb + rg * 4 + r;
        if (gr < NK_TOT) {
            float h = acc[r] * gg + bb;
            g_h[(size_t)gr * 256 + c] = h > 0.f ? h : 0.f;
        }
    }
}

// ---------------- K5c: out = H @ fw2 + b2   [1000x128 @ 256x128] ----
// grid 125: 8 rows x 128 cols per block, 256 threads (2 row-groups x 128 cols)
__global__ void __launch_bounds__(256) fuse_mlp2_kernel(
    const float* __restrict__ fw2, const float* __restrict__ fb2,
    float* __restrict__ outF)
{
    __shared__ float sH[8][260];
    const int tid = threadIdx.x;
    const int rb = blockIdx.x * 8;

    #pragma unroll
    for (int t = 0; t < 2; ++t) {
        int idx = tid + t * 256;        // 0..511 float4s
        int row = idx >> 6, c4 = idx & 63;
        *(float4*)&sH[row][c4 * 4] = *(const float4*)&g_h[(size_t)(rb + row) * 256 + c4 * 4];
    }
    __syncthreads();

    const int cg = tid & 127, rg = tid >> 7;   // col, row group (0..1)
    float acc[4] = {0.f, 0.f, 0.f, 0.f};
    #pragma unroll 4
    for (int i = 0; i < 256; ++i) {
        float w = __ldg(&fw2[i * 128 + cg]);
        #pragma unroll
        for (int r = 0; r < 4; ++r) acc[r] += sH[rg * 4 + r][i] * w;
    }
    const float bb = fb2[cg];
    #pragma unroll
    for (int r = 0; r < 4; ++r) {
        int gr = rb + rg * 4 + r;
        outF[OUT_OFF + (size_t)gr * 128 + cg] = acc[r] + bb;
    }
}

// ---------------- launch ----------------
extern "C" void kernel_launch(void* const* d_in, const int* in_sizes, int n_in,
                              void* d_out, int out_size)
{
    const float* fusion_feat = (const float*)d_in[0];
    const float* src_feat_a  = (const float*)d_in[1];
    const float* src_feat_b  = (const float*)d_in[2];
    const float* heat_w1 = (const float*)d_in[3];
    const float* heat_g1 = (const float*)d_in[4];
    const float* heat_b1 = (const float*)d_in[5];
    const float* heat_w2 = (const float*)d_in[6];
    const float* heat_b2 = (const float*)d_in[7];
    const float* knn_w = (const float*)d_in[8];
    const float* knn_b = (const float*)d_in[9];
    const float* kw_w1 = (const float*)d_in[10];
    const float* kw_g1 = (const float*)d_in[11];
    const float* kw_b1 = (const float*)d_in[12];
    const float* kw_w2 = (const float*)d_in[13];
    const float* kw_b2 = (const float*)d_in[14];
    const float* fuse_w1 = (const float*)d_in[15];
    const float* fuse_g1 = (const float*)d_in[16];
    const float* fuse_b1 = (const float*)d_in[17];
    const float* fuse_w2 = (const float*)d_in[18];
    const float* fuse_b2 = (const float*)d_in[19];
    const int* fusion_coords = (const int*)d_in[20];
    const int* src_coords_a  = (const int*)d_in[21];
    const int* src_coords_b  = (const int*)d_in[22];
    float* outF = (float*)d_out;

    cudaFuncSetAttribute(heat_kernel, cudaFuncAttributeMaxDynamicSharedMemorySize, HEAT_SMEM);
    cudaFuncSetAttribute(topk_kernel, cudaFuncAttributeMaxDynamicSharedMemorySize, TOPK_SMEM);

    heat_kernel<<<NROWS / 64, 256, HEAT_SMEM>>>(fusion_feat, heat_w1, heat_g1,
                                                heat_b1, heat_w2, heat_b2,
                                                src_coords_a, src_coords_b, outF);
    topk_kernel<<<B, 1024, TOPK_SMEM>>>(fusion_coords, outF);
    dim3 kg((NKEY + 7) / 8, B, 2);
    knn_kernel<<<kg, 256>>>(src_feat_a, src_feat_b, knn_w, knn_b);
    fuse_prep_kernel<<<NK_TOT / 8, 256>>>(fusion_feat, kw_w1, kw_g1, kw_b1,
                                          kw_w2, kw_b2);
    dim3 m1((NK_TOT + 15) / 16, 4);
    fuse_mlp1_kernel<<<m1, 256>>>(fuse_w1, fuse_g1, fuse_b1);
    fuse_mlp2_kernel<<<NK_TOT / 8, 256>>>(fuse_w2, fuse_b2, outF);
}

// round 11
// speedup vs baseline: 1.2293x; 1.1697x over previous
#include <cuda_runtime.h>
#include <math.h>

#define B 2
#define NF 20000
#define NS 30000
#define C 128
#define NKEY 500
#define NROWS (B*NF)
#define NK_TOT (B*NKEY)   // 1000

// output layout (flattened, float32, in reference return order)
#define OUT_OFF  0        // (1000,128)
#define KVI_OFF  128000   // (1000,3)
#define HEAT_OFF 131000   // (40000,)
#define S10_OFF  171000   // (40000,10)
#define KC_OFF   571000   // (1000,)

// spatial binning params (cell > radius with wide margin -> 3x3 ring suffices)
#define DIM0 36
#define CELL0 3.0f
#define DIM1 22
#define CELL1 5.0f
#define NCELLMAX (DIM0*DIM0)   // 1296
#define CAP 192                // fixed per-cell capacity (avg 23 / 62; huge margin)

#define SENT 0xFFFFFFFFFFFFFFFFull
#define INVIDX 0xFFFFFFFFu

// ---------------- scratch (device globals; no allocs allowed) ----------------
// g_cellcnt is zeroed by cellreset_kernel at the START of every launch
// sequence (clears the previous call's counts; first call is zero-initialized).
__device__ float g_sig[NROWS];
__device__ int   g_cls[NROWS];
__device__ int   g_topk[NK_TOT];
__device__ float2 g_keyworld[NK_TOT];
__device__ int    g_cellcnt[2][B][NCELLMAX];
__device__ float4 g_cellpts[2][B][NCELLMAX*CAP];   // {wx, wy, idx-bits, 0}

__device__ __forceinline__ float worldc(int c, float stride) {
    // ((c + 0.5) * stride) * 0.075 + (-54), each op fp32-rounded, no contraction
    float t = __fadd_rn((float)c, 0.5f);
    t = __fmul_rn(t, stride);
    t = __fmul_rn(t, 0.075f);
    return __fadd_rn(t, -54.0f);
}

// ---------------- K0: zero cell counts (before this call's bin build) --------
__global__ void cellreset_kernel() {
    int i = blockIdx.x * 1024 + threadIdx.x;
    if (i < 2 * B * NCELLMAX) ((int*)g_cellcnt)[i] = 0;
}

// ---------------- K1: heat MLP (40000 x 128 -> 128 relu -> 10) ----------------
// X tile in shared; W1 streamed from L2 (hot, 64KB) -> high occupancy.
// Prologue: spatial-bin build for the KNN stage (192 points per block).
#define SXS 132   // padded row stride for shared X/H
#define HEAT_SMEM ((64*SXS + 128*12 + 64*10) * 4)
#define BIN_PER_BLOCK 192   // 625 blocks * 192 = 120000 = 2*B*NS exactly

__global__ void __launch_bounds__(256) heat_kernel(
    const float* __restrict__ X, const float* __restrict__ W1,
    const float* __restrict__ G1, const float* __restrict__ B1,
    const float* __restrict__ W2, const float* __restrict__ B2v,
    const int* __restrict__ ca, const int* __restrict__ cb,
    float* __restrict__ outF)
{
    extern __shared__ float sm[];
    float* sX  = sm;                     // 64 * SXS
    float* sW2 = sm + 64 * SXS;          // 128 * 12 (padded, cols>=10 zero)
    float* sS  = sW2 + 128 * 12;         // 64 * 10
    const int tid = threadIdx.x;
    const int rowbase = blockIdx.x * 64;

    // ---- bin-build prologue (independent of the MLP work) ----
    if (tid < BIN_PER_BLOCK) {
        int id = blockIdx.x * BIN_PER_BLOCK + tid;
        int src = id / (B * NS);
        int rem = id - src * (B * NS);
        int b = rem / NS, i = rem - b * NS;
        int2 cc = ((const int2*)(src == 0 ? ca : cb))[b * NS + i];
        float stride = (src == 0) ? 4.0f : 8.0f;
        float wx = worldc(cc.x, stride), wy = worldc(cc.y, stride);
        float cell = (src == 0) ? CELL0 : CELL1;
        int dim = (src == 0) ? DIM0 : DIM1;
        int cx = min(dim - 1, max(0, (int)floorf((wx + 54.0f) / cell)));
        int cy = min(dim - 1, max(0, (int)floorf((wy + 54.0f) / cell)));
        int cid = cy * dim + cx;
        int pos = atomicAdd(&g_cellcnt[src][b][cid], 1);
        if (pos < CAP)
            g_cellpts[src][b][cid * CAP + pos] =
                make_float4(wx, wy, __uint_as_float((unsigned)i), 0.f);
    }

    // load X tile (64x128) into padded shared
    {
        const float4* s = (const float4*)(X + (size_t)rowbase * C);
        #pragma unroll
        for (int t = 0; t < 8; ++t) {
            int idx = tid + t * 256;         // 0..2047 float4s
            int row = idx >> 5, c4 = idx & 31;
            *(float4*)(sX + row * SXS + c4 * 4) = s[idx];
        }
    }
    // load W2 padded to 12 cols
    for (int t = tid; t < 128 * 12; t += 256) {
        int i = t / 12, c = t - i * 12;
        sW2[t] = (c < 10) ? W2[i * 10 + c] : 0.f;
    }
    __syncthreads();

    // 16 thread-rows x 16 thread-cols; 4x8 micro-tile per thread
    const int ty = tid >> 4, tx = tid & 15;
    const int r0 = ty * 4, c0 = tx * 8;
    float acc[4][8];
    #pragma unroll
    for (int i = 0; i < 4; ++i)
        #pragma unroll
        for (int j = 0; j < 8; ++j) acc[i][j] = 0.f;

    #pragma unroll 2
    for (int k = 0; k < 128; k += 4) {
        float4 w[8];
        #pragma unroll
        for (int kk = 0; kk < 4; ++kk) {
            w[2*kk]   = __ldg((const float4*)(W1 + (k + kk) * 128 + c0));
            w[2*kk+1] = __ldg((const float4*)(W1 + (k + kk) * 128 + c0 + 4));
        }
        float4 xr[4];
        #pragma unroll
        for (int i = 0; i < 4; ++i)
            xr[i] = *(const float4*)&sX[(r0 + i) * SXS + k];
        #pragma unroll
        for (int kk = 0; kk < 4; ++kk) {
            #pragma unroll
            for (int i = 0; i < 4; ++i) {
                float x = (kk == 0) ? xr[i].x : (kk == 1) ? xr[i].y
                        : (kk == 2) ? xr[i].z : xr[i].w;
                acc[i][0] += x * w[2*kk].x;   acc[i][1] += x * w[2*kk].y;
                acc[i][2] += x * w[2*kk].z;   acc[i][3] += x * w[2*kk].w;
                acc[i][4] += x * w[2*kk+1].x; acc[i][5] += x * w[2*kk+1].y;
                acc[i][6] += x * w[2*kk+1].z; acc[i][7] += x * w[2*kk+1].w;
            }
        }
    }
    float4 ga = *(const float4*)&G1[c0], gb = *(const float4*)&G1[c0 + 4];
    float4 ba = *(const float4*)&B1[c0], bb = *(const float4*)&B1[c0 + 4];
    float gv[8] = {ga.x, ga.y, ga.z, ga.w, gb.x, gb.y, gb.z, gb.w};
    float bv[8] = {ba.x, ba.y, ba.z, ba.w, bb.x, bb.y, bb.z, bb.w};
    __syncthreads();  // all reads of sX done; safe to overwrite with H
    #pragma unroll
    for (int i = 0; i < 4; ++i)
        #pragma unroll
        for (int j = 0; j < 8; ++j) {
            float h = acc[i][j] * gv[j] + bv[j];
            sX[(r0 + i) * SXS + c0 + j] = h > 0.f ? h : 0.f;
        }
    __syncthreads();

    // stage 2: scores10 = H @ W2 + b2  (2 threads per row, 5 cols each)
    if (tid < 128) {
        const int r = tid >> 1, hhalf = tid & 1;
        const int cc0 = hhalf * 5;
        float a[5] = {0.f, 0.f, 0.f, 0.f, 0.f};
        for (int i = 0; i < 128; ++i) {
            float hv = sX[r * SXS + i];
            #pragma unroll
            for (int q = 0; q < 5; ++q) a[q] += hv * sW2[i * 12 + cc0 + q];
        }
        #pragma unroll
        for (int q = 0; q < 5; ++q) {
            int c = cc0 + q;
            float v = a[q] + B2v[c];
            outF[S10_OFF + (size_t)(rowbase + r) * 10 + c] = v;
            sS[r * 10 + c] = v;
        }
    }
    __syncthreads();
    if (tid < 64) {
        int r = tid, row = rowbase + r;
        float m = -INFINITY; int a = 0;
        #pragma unroll
        for (int c = 0; c < 10; ++c) {
            float v = sS[r * 10 + c];
            if (v > m) { m = v; a = c; }   // first max wins (jnp.argmax)
        }
        outF[HEAT_OFF + row] = m;
        g_sig[row] = 1.f / (1.f + expf(-m));
        g_cls[row] = a;
    }
}

// ---------------- K2: per-batch top-500 (jax.lax.top_k semantics) ----------------
#define VPT 20          // values per thread: 20*1024 >= NF
#define CANDMAX 2048
#define TOPK_SMEM (CANDMAX * 8)

__global__ void __launch_bounds__(1024) topk_kernel(
    const int* __restrict__ fusion_coords, float* __restrict__ outF)
{
    extern __shared__ unsigned char dsm[];
    unsigned long long* cand = (unsigned long long*)dsm;   // CANDMAX
    __shared__ int s_cnt[32];   // one counter per binary-search iteration
    __shared__ int s_n;
    const int tid = threadIdx.x;
    const int lane = tid & 31;
    const int b = blockIdx.x;

    // load scores into registers
    unsigned vals[VPT];
    #pragma unroll
    for (int t = 0; t < VPT; ++t) {
        int i = tid + t * 1024;
        vals[t] = (i < NF) ? __float_as_uint(g_sig[b * NF + i]) : 0u;
    }
    if (tid < 32) s_cnt[tid] = 0;
    if (tid == 0) s_n = 0;
    cand[tid] = 0ull;
    cand[tid + 1024] = 0ull;
    __syncthreads();

    // binary search: max thr with count(bits >= thr) >= NKEY.
    unsigned lo = 0u, hi = 0x3F800000u;
    #pragma unroll 1
    for (int it = 0; it < 31; ++it) {
        unsigned mid = lo + ((hi - lo) >> 1);
        int c = 0;
        #pragma unroll
        for (int t = 0; t < VPT; ++t) c += (vals[t] >= mid) ? 1 : 0;
        #pragma unroll
        for (int o = 16; o; o >>= 1) c += __shfl_xor_sync(0xffffffffu, c, o);
        if (lane == 0 && c) atomicAdd(&s_cnt[it], c);
        __syncthreads();
        if (s_cnt[it] >= NKEY) lo = mid; else hi = mid;
    }
    const unsigned thr = lo;

    // collect candidates >= thr as packed keys (value desc, tie -> lower idx)
    #pragma unroll
    for (int t = 0; t < VPT; ++t) {
        unsigned v = vals[t];
        if (v >= thr) {
            int i = tid + t * 1024;
            int p = atomicAdd(&s_n, 1);
            if (p < CANDMAX)
                cand[p] = ((unsigned long long)v << 32) |
                          (unsigned long long)(0xFFFFFFFFu - (unsigned)i);
        }
    }
    __syncthreads();
    int n = s_n; if (n > CANDMAX) n = CANDMAX;

    // rank-by-count: keys are unique (idx embedded), rank = #{j : cand[j] > mine}
    for (int s = tid; s < CANDMAX; s += 1024) {
        unsigned long long mine = cand[s];
        if (mine == 0ull || s >= n) continue;
        int rank = 0;
        for (int j = 0; j < n; ++j) rank += (cand[j] > mine) ? 1 : 0;
        if (rank < NKEY) {
            unsigned idx = 0xFFFFFFFFu - (unsigned)(mine & 0xFFFFFFFFull);
            g_topk[b * NKEY + rank] = (int)idx;
            int2 cc = ((const int2*)fusion_coords)[b * NF + (int)idx];
            int o = (b * NKEY + rank) * 3;
            outF[KVI_OFF + o + 0] = (float)b;
            outF[KVI_OFF + o + 1] = (float)cc.x;
            outF[KVI_OFF + o + 2] = (float)cc.y;
            g_keyworld[b * NKEY + rank] = make_float2(worldc(cc.x, 8.0f), worldc(cc.y, 8.0f));
            outF[KC_OFF + b * NKEY + rank] = (float)g_cls[b * NF + (int)idx];
        }
    }
}

// ---------------- K3: MEGAFUSE — knn + kwMLP + softmax + fuse MLPs -----------
// One block = 8 consecutive global keys. 512 threads:
//   phase 1: 16 warps run the 16 (key, src) knn tasks -> smem mf
//   phase 2: kw MLP + softmax + fused-vector build (all in smem)
//   phase 3: fused @ fw1 (BN+ReLU) -> smem H;  H @ fw2 + b2 -> out
__global__ void __launch_bounds__(512) megafuse_kernel(
    const float* __restrict__ fa, const float* __restrict__ fb,
    const float* __restrict__ knn_w, const float* __restrict__ knn_b,
    const float* __restrict__ fusion_feat,
    const float* __restrict__ kw1, const float* __restrict__ kg1,
    const float* __restrict__ kb1, const float* __restrict__ kw2,
    const float* __restrict__ kb2,
    const float* __restrict__ fw1, const float* __restrict__ fg1,
    const float* __restrict__ fb1, const float* __restrict__ fw2,
    const float* __restrict__ fb2, float* __restrict__ outF)
{
    __shared__ float smf[2][8][128];
    __shared__ float kf[8][128];
    __shared__ float h64[8][64];
    __shared__ float logit[8][3];
    __shared__ float swx[8][3];
    __shared__ float sF[8][260];
    __shared__ float sH[8][260];

    const int tid = threadIdx.x;
    const int w = tid >> 5, lane = tid & 31;
    const int g0 = blockIdx.x * 8;

    // kf gather (independent of knn; 1024 elements, 2 per thread)
    for (int t = tid; t < 1024; t += 512) {
        int k = t >> 7, c = t & 127;
        int g = g0 + k;
        int b = g / NKEY;
        int ki = g_topk[g];
        kf[k][c] = fusion_feat[((size_t)b * NF + ki) * C + c];
    }

    // ---- phase 1: knn. warp w -> key g0+(w>>1), src w&1 ----
    {
        const int klocal = w >> 1;
        const int src = w & 1;
        const int g = g0 + klocal;
        const int b = g / NKEY;
        float2 kw = g_keyworld[g];
        const float kx = kw.x, ky = kw.y;
        const float r2 = (src == 0) ? 5.76f : 23.04f;
        const float cell = (src == 0) ? CELL0 : CELL1;
        const int dim = (src == 0) ? DIM0 : DIM1;
        int cx = min(dim - 1, max(0, (int)floorf((kx + 54.0f) / cell)));
        int cy = min(dim - 1, max(0, (int)floorf((ky + 54.0f) / cell)));

        const int* ccnt = g_cellcnt[src][b];
        const float4* cpts = g_cellpts[src][b];

        int cids[9];
        int cnts[9];
        int ncell = 0;
        #pragma unroll
        for (int dy = -1; dy <= 1; ++dy) {
            int yy = cy + dy;
            if (yy < 0 || yy >= dim) continue;
            #pragma unroll
            for (int dx = -1; dx <= 1; ++dx) {
                int xx = cx + dx;
                if (xx < 0 || xx >= dim) continue;
                int cid = yy * dim + xx;
                cids[ncell] = cid;
                cnts[ncell] = min(ccnt[cid], CAP);
                ++ncell;
            }
        }

        unsigned long long lst[16];
        #pragma unroll
        for (int q = 0; q < 16; ++q) lst[q] = SENT;

        for (int cc = 0; cc < ncell; ++cc) {
            const int e = cnts[cc];
            const float4* cp = cpts + cids[cc] * CAP;
            for (int i = lane; i < e; i += 32) {
                float4 p = cp[i];
                float ddx = kx - p.x;
                float ddy = ky - p.y;
                float d2 = __fadd_rn(__fmul_rn(ddx, ddx), __fmul_rn(ddy, ddy));
                if (d2 <= r2) {
                    unsigned long long kk =
                        ((unsigned long long)__float_as_uint(d2) << 32) |
                        (unsigned long long)__float_as_uint(p.z);
                    if (kk < lst[15]) {
                        unsigned long long cur = kk;
                        #pragma unroll
                        for (int q = 0; q < 16; ++q) {
                            unsigned long long mn = lst[q] < cur ? lst[q] : cur;
                            cur = lst[q] < cur ? cur : lst[q];
                            lst[q] = mn;
                        }
                    }
                }
            }
        }

        // warp merge: 16 globally-smallest keys into static registers
        unsigned nIdx[16];
        #pragma unroll
        for (int r = 0; r < 16; ++r) {
            unsigned long long mine = lst[0];
            unsigned long long best = mine;
            #pragma unroll
            for (int o = 16; o; o >>= 1) {
                unsigned long long other = __shfl_xor_sync(0xffffffffu, best, o);
                best = other < best ? other : best;
            }
            unsigned msk = __ballot_sync(0xffffffffu, mine == best);
            if (lane == __ffs((int)msk) - 1) {
                #pragma unroll
                for (int q = 0; q < 15; ++q) lst[q] = lst[q + 1];
                lst[15] = SENT;
            }
            nIdx[r] = (best == SENT) ? INVIDX : (unsigned)(best & 0xFFFFFFFFull);
        }

        // batched gather: 16 independent feature-row loads in flight
        const float* feat = ((src == 0) ? fa : fb) + (size_t)b * NS * C;
        float4 acc = make_float4(0.f, 0.f, 0.f, 0.f);
        #pragma unroll
        for (int r = 0; r < 16; ++r) {
            unsigned idx = nIdx[r];
            unsigned safe = (idx == INVIDX) ? 0u : idx;
            float ww = (idx == INVIDX) ? 0.f : __ldg(&knn_w[src * 16 + r]);
            float4 v = *(const float4*)(feat + (size_t)safe * C + lane * 4);
            acc.x += ww * v.x; acc.y += ww * v.y; acc.z += ww * v.z; acc.w += ww * v.w;
        }
        float bb = knn_b[src];
        float* dst = &smf[src][klocal][lane * 4];
        dst[0] = acc.x + bb; dst[1] = acc.y + bb; dst[2] = acc.z + bb; dst[3] = acc.w + bb;
    }
    __syncthreads();

    // ---- phase 2: kw MLP (8x128 @ 128x64), logits, softmax, fused build ----
    {
        int k = tid >> 6, j = tid & 63;
        float a = 0.f;
        #pragma unroll 4
        for (int i = 0; i < 128; ++i) a += kf[k][i] * __ldg(&kw1[i * 64 + j]);
        a = a * kg1[j] + kb1[j];
        h64[k][j] = a > 0.f ? a : 0.f;
    }
    __syncthreads();
    if (tid < 24) {
        int k = tid / 3, j = tid - k * 3;
        float a = 0.f;
        #pragma unroll 4
        for (int i = 0; i < 64; ++i) a += h64[k][i] * kw2[i * 3 + j];
        logit[k][j] = a + kb2[j];
    }
    __syncthreads();
    if (tid < 8) {
        float l0 = logit[tid][0], l1 = logit[tid][1], l2 = logit[tid][2];
        float m = fmaxf(l0, fmaxf(l1, l2));
        float e0 = expf(l0 - m), e1 = expf(l1 - m), e2 = expf(l2 - m);
        float s = e0 + e1 + e2;
        swx[tid][0] = e0 / s; swx[tid][1] = e1 / s; swx[tid][2] = e2 / s;
    }
    __syncthreads();
    for (int t = tid; t < 1024; t += 512) {
        int k = t >> 7, c = t & 127;
        float x = kf[k][c];
        float kv = swx[k][0] * x;
        float fs = kv * smf[0][k][c];
        kv = swx[k][1] * kv;
        fs += kv * smf[1][k][c];
        sF[k][c] = fs;
        sF[k][128 + c] = kv;
    }
    __syncthreads();

    // ---- phase 3a: H = relu((sF @ fw1)*g + b)  [8x256 @ 256x256] ----
    {
        const int c = tid & 255, rh = tid >> 8;   // rh = 0/1 -> rows rh*4..+3
        float acc[4] = {0.f, 0.f, 0.f, 0.f};
        #pragma unroll 2
        for (int i4 = 0; i4 < 64; ++i4) {
            float4 xv[4];
            #pragma unroll
            for (int r = 0; r < 4; ++r)
                xv[r] = *(const float4*)&sF[rh * 4 + r][i4 * 4];
            #pragma unroll
            for (int kk = 0; kk < 4; ++kk) {
                float wv = __ldg(&fw1[(i4 * 4 + kk) * 256 + c]);
                #pragma unroll
                for (int r = 0; r < 4; ++r) {
                    float x = (kk == 0) ? xv[r].x : (kk == 1) ? xv[r].y
                            : (kk == 2) ? xv[r].z : xv[r].w;
                    acc[r] += x * wv;
                }
            }
        }
        const float gg = fg1[c], bb = fb1[c];
        #pragma unroll
        for (int r = 0; r < 4; ++r) {
            float h = acc[r] * gg + bb;
            sH[rh * 4 + r][c] = h > 0.f ? h : 0.f;
        }
    }
    __syncthreads();

    // ---- phase 3b: out = sH @ fw2 + b2  [8x256 @ 256x128] ----
    {
        const int c = tid & 127, rq = tid >> 7;   // rq = 0..3 -> rows rq*2, rq*2+1
        float a0 = 0.f, a1 = 0.f;
        #pragma unroll 2
        for (int i4 = 0; i4 < 64; ++i4) {
            float4 x0 = *(const float4*)&sH[rq * 2][i4 * 4];
            float4 x1 = *(const float4*)&sH[rq * 2 + 1][i4 * 4];
            #pragma unroll
            for (int kk = 0; kk < 4; ++kk) {
                float wv = __ldg(&fw2[(i4 * 4 + kk) * 128 + c]);
                float v0 = (kk == 0) ? x0.x : (kk == 1) ? x0.y : (kk == 2) ? x0.z : x0.w;
                float v1 = (kk == 0) ? x1.x : (kk == 1) ? x1.y : (kk == 2) ? x1.z : x1.w;
                a0 += v0 * wv;
                a1 += v1 * wv;
            }
        }
        const float bb = fb2[c];
        outF[OUT_OFF + (size_t)(g0 + rq * 2) * 128 + c]     = a0 + bb;
        outF[OUT_OFF + (size_t)(g0 + rq * 2 + 1) * 128 + c] = a1 + bb;
    }
}

// ---------------- launch ----------------
extern "C" void kernel_launch(void* const* d_in, const int* in_sizes, int n_in,
                              void* d_out, int out_size)
{
    const float* fusion_feat = (const float*)d_in[0];
    const float* src_feat_a  = (const float*)d_in[1];
    const float* src_feat_b  = (const float*)d_in[2];
    const float* heat_w1 = (const float*)d_in[3];
    const float* heat_g1 = (const float*)d_in[4];
    const float* heat_b1 = (const float*)d_in[5];
    const float* heat_w2 = (const float*)d_in[6];
    const float* heat_b2 = (const float*)d_in[7];
    const float* knn_w = (const float*)d_in[8];
    const float* knn_b = (const float*)d_in[9];
    const float* kw_w1 = (const float*)d_in[10];
    const float* kw_g1 = (const float*)d_in[11];
    const float* kw_b1 = (const float*)d_in[12];
    const float* kw_w2 = (const float*)d_in[13];
    const float* kw_b2 = (const float*)d_in[14];
    const float* fuse_w1 = (const float*)d_in[15];
    const float* fuse_g1 = (const float*)d_in[16];
    const float* fuse_b1 = (const float*)d_in[17];
    const float* fuse_w2 = (const float*)d_in[18];
    const float* fuse_b2 = (const float*)d_in[19];
    const int* fusion_coords = (const int*)d_in[20];
    const int* src_coords_a  = (const int*)d_in[21];
    const int* src_coords_b  = (const int*)d_in[22];
    float* outF = (float*)d_out;

    cudaFuncSetAttribute(heat_kernel, cudaFuncAttributeMaxDynamicSharedMemorySize, HEAT_SMEM);
    cudaFuncSetAttribute(topk_kernel, cudaFuncAttributeMaxDynamicSharedMemorySize, TOPK_SMEM);

    cellreset_kernel<<<(2 * B * NCELLMAX + 1023) / 1024, 1024>>>();
    heat_kernel<<<NROWS / 64, 256, HEAT_SMEM>>>(fusion_feat, heat_w1, heat_g1,
                                                heat_b1, heat_w2, heat_b2,
                                                src_coords_a, src_coords_b, outF);
    topk_kernel<<<B, 1024, TOPK_SMEM>>>(fusion_coords, outF);
    megafuse_kernel<<<NK_TOT / 8, 512>>>(src_feat_a, src_feat_b, knn_w, knn_b,
                                         fusion_feat, kw_w1, kw_g1, kw_b1,
                                         kw_w2, kw_b2, fuse_w1, fuse_g1,
                                         fuse_b1, fuse_w2, fuse_b2, outF);
}

// round 14
// speedup vs baseline: 1.2821x; 1.0429x over previous
#include <cuda_runtime.h>
#include <math.h>

#define B 2
#define NF 20000
#define NS 30000
#define C 128
#define NKEY 500
#define NROWS (B*NF)
#define NK_TOT (B*NKEY)   // 1000

// output layout (flattened, float32, in reference return order)
#define OUT_OFF  0        // (1000,128)
#define KVI_OFF  128000   // (1000,3)
#define HEAT_OFF 131000   // (40000,)
#define S10_OFF  171000   // (40000,10)
#define KC_OFF   571000   // (1000,)

// spatial binning params (cell > radius with wide margin -> 3x3 ring suffices)
#define DIM0 36
#define CELL0 3.0f
#define DIM1 22
#define CELL1 5.0f
#define NCELLMAX (DIM0*DIM0)   // 1296
#define CAP 192                // fixed per-cell capacity (avg 23 / 62; huge margin)

#define SENT 0xFFFFFFFFFFFFFFFFull
#define INVIDX 0xFFFFFFFFu

// ---------------- scratch (device globals; no allocs allowed) ----------------
__device__ float g_sig[NROWS];
__device__ int   g_cls[NROWS];
__device__ int   g_topk[NK_TOT];
__device__ float2 g_keyworld[NK_TOT];
__device__ int    g_cellcnt[2][B][NCELLMAX];
__device__ float4 g_cellpts[2][B][NCELLMAX*CAP];   // {wx, wy, idx-bits, 0}

__device__ __forceinline__ float worldc(int c, float stride) {
    float t = __fadd_rn((float)c, 0.5f);
    t = __fmul_rn(t, stride);
    t = __fmul_rn(t, 0.075f);
    return __fadd_rn(t, -54.0f);
}

// ---------------- K0: zero cell counts (before this call's bin build) --------
__global__ void cellreset_kernel() {
    int i = blockIdx.x * 1024 + threadIdx.x;
    if (i < 2 * B * NCELLMAX) ((int*)g_cellcnt)[i] = 0;
}

// ---------------- K1: heat MLP (40000 x 128 -> 128 relu -> 10) ----------------
#define SXS 132
#define HEAT_SMEM ((64*SXS + 128*12 + 64*10) * 4)
#define BIN_PER_BLOCK 192   // 625 blocks * 192 = 120000 = 2*B*NS exactly

__global__ void __launch_bounds__(256) heat_kernel(
    const float* __restrict__ X, const float* __restrict__ W1,
    const float* __restrict__ G1, const float* __restrict__ B1,
    const float* __restrict__ W2, const float* __restrict__ B2v,
    const int* __restrict__ ca, const int* __restrict__ cb,
    float* __restrict__ outF)
{
    extern __shared__ float sm[];
    float* sX  = sm;                     // 64 * SXS
    float* sW2 = sm + 64 * SXS;          // 128 * 12
    float* sS  = sW2 + 128 * 12;         // 64 * 10
    const int tid = threadIdx.x;
    const int rowbase = blockIdx.x * 64;

    // ---- bin-build prologue ----
    if (tid < BIN_PER_BLOCK) {
        int id = blockIdx.x * BIN_PER_BLOCK + tid;
        int src = id / (B * NS);
        int rem = id - src * (B * NS);
        int b = rem / NS, i = rem - b * NS;
        int2 cc = ((const int2*)(src == 0 ? ca : cb))[b * NS + i];
        float stride = (src == 0) ? 4.0f : 8.0f;
        float wx = worldc(cc.x, stride), wy = worldc(cc.y, stride);
        float cell = (src == 0) ? CELL0 : CELL1;
        int dim = (src == 0) ? DIM0 : DIM1;
        int cx = min(dim - 1, max(0, (int)floorf((wx + 54.0f) / cell)));
        int cy = min(dim - 1, max(0, (int)floorf((wy + 54.0f) / cell)));
        int cid = cy * dim + cx;
        int pos = atomicAdd(&g_cellcnt[src][b][cid], 1);
        if (pos < CAP)
            g_cellpts[src][b][cid * CAP + pos] =
                make_float4(wx, wy, __uint_as_float((unsigned)i), 0.f);
    }

    {
        const float4* s = (const float4*)(X + (size_t)rowbase * C);
        #pragma unroll
        for (int t = 0; t < 8; ++t) {
            int idx = tid + t * 256;
            int row = idx >> 5, c4 = idx & 31;
            *(float4*)(sX + row * SXS + c4 * 4) = s[idx];
        }
    }
    for (int t = tid; t < 128 * 12; t += 256) {
        int i = t / 12, c = t - i * 12;
        sW2[t] = (c < 10) ? W2[i * 10 + c] : 0.f;
    }
    __syncthreads();

    const int ty = tid >> 4, tx = tid & 15;
    const int r0 = ty * 4, c0 = tx * 8;
    float acc[4][8];
    #pragma unroll
    for (int i = 0; i < 4; ++i)
        #pragma unroll
        for (int j = 0; j < 8; ++j) acc[i][j] = 0.f;

    #pragma unroll 2
    for (int k = 0; k < 128; k += 4) {
        float4 w[8];
        #pragma unroll
        for (int kk = 0; kk < 4; ++kk) {
            w[2*kk]   = __ldg((const float4*)(W1 + (k + kk) * 128 + c0));
            w[2*kk+1] = __ldg((const float4*)(W1 + (k + kk) * 128 + c0 + 4));
        }
        float4 xr[4];
        #pragma unroll
        for (int i = 0; i < 4; ++i)
            xr[i] = *(const float4*)&sX[(r0 + i) * SXS + k];
        #pragma unroll
        for (int kk = 0; kk < 4; ++kk) {
            #pragma unroll
            for (int i = 0; i < 4; ++i) {
                float x = (kk == 0) ? xr[i].x : (kk == 1) ? xr[i].y
                        : (kk == 2) ? xr[i].z : xr[i].w;
                acc[i][0] += x * w[2*kk].x;   acc[i][1] += x * w[2*kk].y;
                acc[i][2] += x * w[2*kk].z;   acc[i][3] += x * w[2*kk].w;
                acc[i][4] += x * w[2*kk+1].x; acc[i][5] += x * w[2*kk+1].y;
                acc[i][6] += x * w[2*kk+1].z; acc[i][7] += x * w[2*kk+1].w;
            }
        }
    }
    float4 ga = *(const float4*)&G1[c0], gb = *(const float4*)&G1[c0 + 4];
    float4 ba = *(const float4*)&B1[c0], bb = *(const float4*)&B1[c0 + 4];
    float gv[8] = {ga.x, ga.y, ga.z, ga.w, gb.x, gb.y, gb.z, gb.w};
    float bv[8] = {ba.x, ba.y, ba.z, ba.w, bb.x, bb.y, bb.z, bb.w};
    __syncthreads();
    #pragma unroll
    for (int i = 0; i < 4; ++i)
        #pragma unroll
        for (int j = 0; j < 8; ++j) {
            float h = acc[i][j] * gv[j] + bv[j];
            sX[(r0 + i) * SXS + c0 + j] = h > 0.f ? h : 0.f;
        }
    __syncthreads();

    if (tid < 128) {
        const int r = tid >> 1, hhalf = tid & 1;
        const int cc0 = hhalf * 5;
        float a[5] = {0.f, 0.f, 0.f, 0.f, 0.f};
        for (int i = 0; i < 128; ++i) {
            float hv = sX[r * SXS + i];
            #pragma unroll
            for (int q = 0; q < 5; ++q) a[q] += hv * sW2[i * 12 + cc0 + q];
        }
        #pragma unroll
        for (int q = 0; q < 5; ++q) {
            int c = cc0 + q;
            float v = a[q] + B2v[c];
            outF[S10_OFF + (size_t)(rowbase + r) * 10 + c] = v;
            sS[r * 10 + c] = v;
        }
    }
    __syncthreads();
    if (tid < 64) {
        int r = tid, row = rowbase + r;
        float m = -INFINITY; int a = 0;
        #pragma unroll
        for (int c = 0; c < 10; ++c) {
            float v = sS[r * 10 + c];
            if (v > m) { m = v; a = c; }
        }
        outF[HEAT_OFF + row] = m;
        g_sig[row] = 1.f / (1.f + expf(-m));
        g_cls[row] = a;
    }
}

// ---------------- K2: per-batch top-500 (jax.lax.top_k semantics) ----------------
#define VPT 20
#define CANDMAX 2048
#define TOPK_SMEM (CANDMAX * 8)

__global__ void __launch_bounds__(1024) topk_kernel(
    const int* __restrict__ fusion_coords, float* __restrict__ outF)
{
    extern __shared__ unsigned char dsm[];
    unsigned long long* cand = (unsigned long long*)dsm;
    __shared__ int s_cnt[32];
    __shared__ int s_n;
    const int tid = threadIdx.x;
    const int lane = tid & 31;
    const int b = blockIdx.x;

    unsigned vals[VPT];
    #pragma unroll
    for (int t = 0; t < VPT; ++t) {
        int i = tid + t * 1024;
        vals[t] = (i < NF) ? __float_as_uint(g_sig[b * NF + i]) : 0u;
    }
    if (tid < 32) s_cnt[tid] = 0;
    if (tid == 0) s_n = 0;
    cand[tid] = 0ull;
    cand[tid + 1024] = 0ull;
    __syncthreads();

    unsigned lo = 0u, hi = 0x3F800000u;
    #pragma unroll 1
    for (int it = 0; it < 31; ++it) {
        unsigned mid = lo + ((hi - lo) >> 1);
        int c = 0;
        #pragma unroll
        for (int t = 0; t < VPT; ++t) c += (vals[t] >= mid) ? 1 : 0;
        #pragma unroll
        for (int o = 16; o; o >>= 1) c += __shfl_xor_sync(0xffffffffu, c, o);
        if (lane == 0 && c) atomicAdd(&s_cnt[it], c);
        __syncthreads();
        if (s_cnt[it] >= NKEY) lo = mid; else hi = mid;
    }
    const unsigned thr = lo;

    #pragma unroll
    for (int t = 0; t < VPT; ++t) {
        unsigned v = vals[t];
        if (v >= thr) {
            int i = tid + t * 1024;
            int p = atomicAdd(&s_n, 1);
            if (p < CANDMAX)
                cand[p] = ((unsigned long long)v << 32) |
                          (unsigned long long)(0xFFFFFFFFu - (unsigned)i);
        }
    }
    __syncthreads();
    int n = s_n; if (n > CANDMAX) n = CANDMAX;

    for (int s = tid; s < CANDMAX; s += 1024) {
        unsigned long long mine = cand[s];
        if (mine == 0ull || s >= n) continue;
        int rank = 0;
        for (int j = 0; j < n; ++j) rank += (cand[j] > mine) ? 1 : 0;
        if (rank < NKEY) {
            unsigned idx = 0xFFFFFFFFu - (unsigned)(mine & 0xFFFFFFFFull);
            g_topk[b * NKEY + rank] = (int)idx;
            int2 cc = ((const int2*)fusion_coords)[b * NF + (int)idx];
            int o = (b * NKEY + rank) * 3;
            outF[KVI_OFF + o + 0] = (float)b;
            outF[KVI_OFF + o + 1] = (float)cc.x;
            outF[KVI_OFF + o + 2] = (float)cc.y;
            g_keyworld[b * NKEY + rank] = make_float2(worldc(cc.x, 8.0f), worldc(cc.y, 8.0f));
            outF[KC_OFF + b * NKEY + rank] = (float)g_cls[b * NF + (int)idx];
        }
    }
}

// ---------------- K3: MEGAFUSE — 4 keys/block, grid 250, 512 threads ---------
// phase 1: warps 0-7 run 8 (key,src) knn tasks; warps 8-15 gather kf (overlap)
// phase 2: kw MLP + softmax + fused build
// phase 3a: k-split GEMM (128-deep chains) + smem combine -> H
// phase 3b: H @ fw2 + b2 -> out
#define KPB 4   // keys per block

__global__ void __launch_bounds__(512) megafuse_kernel(
    const float* __restrict__ fa, const float* __restrict__ fb,
    const float* __restrict__ knn_w, const float* __restrict__ knn_b,
    const float* __restrict__ fusion_feat,
    const float* __restrict__ kw1, const float* __restrict__ kg1,
    const float* __restrict__ kb1, const float* __restrict__ kw2,
    const float* __restrict__ kb2,
    const float* __restrict__ fw1, const float* __restrict__ fg1,
    const float* __restrict__ fb1, const float* __restrict__ fw2,
    const float* __restrict__ fb2, float* __restrict__ outF)
{
    __shared__ float smf[2][KPB][128];
    __shared__ float kf[KPB][128];
    __shared__ float h64[KPB][64];
    __shared__ float logit[KPB][3];
    __shared__ float swx[KPB][3];
    __shared__ float sF[KPB][260];
    __shared__ float pH[2][KPB][260];   // k-split partials
    __shared__ float sH[KPB][260];

    const int tid = threadIdx.x;
    const int w = tid >> 5, lane = tid & 31;
    const int g0 = blockIdx.x * KPB;

    // ---- phase 1 (warps 8-15): kf gather — 4x128 = 512 elements, 1/thread
    if (w >= 8) {
        int t = (w - 8) * 32 + lane;     // 0..255 -> elements t and t+256
        #pragma unroll
        for (int q = 0; q < 2; ++q) {
            int idx = t + q * 256;
            int k = idx >> 7, c = idx & 127;
            int g = g0 + k;
            int b = g / NKEY;
            int ki = g_topk[g];
            kf[k][c] = fusion_feat[((size_t)b * NF + ki) * C + c];
        }
    } else {
        // ---- phase 1 (warps 0-7): knn. warp w -> key g0+(w>>1), src w&1 ----
        const int klocal = w >> 1;
        const int src = w & 1;
        const int g = g0 + klocal;
        const int b = g / NKEY;
        float2 kw = g_keyworld[g];
        const float kx = kw.x, ky = kw.y;
        const float r2 = (src == 0) ? 5.76f : 23.04f;
        const float cell = (src == 0) ? CELL0 : CELL1;
        const int dim = (src == 0) ? DIM0 : DIM1;
        int cx = min(dim - 1, max(0, (int)floorf((kx + 54.0f) / cell)));
        int cy = min(dim - 1, max(0, (int)floorf((ky + 54.0f) / cell)));

        const int* ccnt = g_cellcnt[src][b];
        const float4* cpts = g_cellpts[src][b];

        int cids[9];
        int cnts[9];
        int ncell = 0;
        #pragma unroll
        for (int dy = -1; dy <= 1; ++dy) {
            int yy = cy + dy;
            if (yy < 0 || yy >= dim) continue;
            #pragma unroll
            for (int dx = -1; dx <= 1; ++dx) {
                int xx = cx + dx;
                if (xx < 0 || xx >= dim) continue;
                int cid = yy * dim + xx;
                cids[ncell] = cid;
                cnts[ncell] = min(ccnt[cid], CAP);
                ++ncell;
            }
        }

        unsigned long long lst[16];
        #pragma unroll
        for (int q = 0; q < 16; ++q) lst[q] = SENT;

        for (int cc = 0; cc < ncell; ++cc) {
            const int e = cnts[cc];
            const float4* cp = cpts + cids[cc] * CAP;
            for (int i = lane; i < e; i += 32) {
                float4 p = cp[i];
                float ddx = kx - p.x;
                float ddy = ky - p.y;
                float d2 = __fadd_rn(__fmul_rn(ddx, ddx), __fmul_rn(ddy, ddy));
                if (d2 <= r2) {
                    unsigned long long kk =
                        ((unsigned long long)__float_as_uint(d2) << 32) |
                        (unsigned long long)__float_as_uint(p.z);
                    if (kk < lst[15]) {
                        unsigned long long cur = kk;
                        #pragma unroll
                        for (int q = 0; q < 16; ++q) {
                            unsigned long long mn = lst[q] < cur ? lst[q] : cur;
                            cur = lst[q] < cur ? cur : lst[q];
                            lst[q] = mn;
                        }
                    }
                }
            }
        }

        // warp merge: 16 globally-smallest keys into static registers
        unsigned nIdx[16];
        #pragma unroll
        for (int r = 0; r < 16; ++r) {
            unsigned long long mine = lst[0];
            unsigned long long best = mine;
            #pragma unroll
            for (int o = 16; o; o >>= 1) {
                unsigned long long other = __shfl_xor_sync(0xffffffffu, best, o);
                best = other < best ? other : best;
            }
            unsigned msk = __ballot_sync(0xffffffffu, mine == best);
            if (lane == __ffs((int)msk) - 1) {
                #pragma unroll
                for (int q = 0; q < 15; ++q) lst[q] = lst[q + 1];
                lst[15] = SENT;
            }
            nIdx[r] = (best == SENT) ? INVIDX : (unsigned)(best & 0xFFFFFFFFull);
        }

        // batched gather: 16 independent feature-row loads in flight
        const float* feat = ((src == 0) ? fa : fb) + (size_t)b * NS * C;
        float4 acc = make_float4(0.f, 0.f, 0.f, 0.f);
        #pragma unroll
        for (int r = 0; r < 16; ++r) {
            unsigned idx = nIdx[r];
            unsigned safe = (idx == INVIDX) ? 0u : idx;
            float ww = (idx == INVIDX) ? 0.f : __ldg(&knn_w[src * 16 + r]);
            float4 v = *(const float4*)(feat + (size_t)safe * C + lane * 4);
            acc.x += ww * v.x; acc.y += ww * v.y; acc.z += ww * v.z; acc.w += ww * v.w;
        }
        float bb = knn_b[src];
        float* dst = &smf[src][klocal][lane * 4];
        dst[0] = acc.x + bb; dst[1] = acc.y + bb; dst[2] = acc.z + bb; dst[3] = acc.w + bb;
    }
    __syncthreads();

    // ---- phase 2: kw MLP (4x128 @ 128x64), logits, softmax, fused build ----
    if (tid < 256) {
        int k = tid >> 6, j = tid & 63;
        float a = 0.f;
        #pragma unroll 8
        for (int i = 0; i < 128; ++i) a += kf[k][i] * __ldg(&kw1[i * 64 + j]);
        a = a * kg1[j] + kb1[j];
        h64[k][j] = a > 0.f ? a : 0.f;
    }
    __syncthreads();
    if (tid < 12) {
        int k = tid / 3, j = tid - k * 3;
        float a = 0.f;
        #pragma unroll 8
        for (int i = 0; i < 64; ++i) a += h64[k][i] * kw2[i * 3 + j];
        logit[k][j] = a + kb2[j];
    }
    __syncthreads();
    if (tid < KPB) {
        float l0 = logit[tid][0], l1 = logit[tid][1], l2 = logit[tid][2];
        float m = fmaxf(l0, fmaxf(l1, l2));
        float e0 = expf(l0 - m), e1 = expf(l1 - m), e2 = expf(l2 - m);
        float s = e0 + e1 + e2;
        swx[tid][0] = e0 / s; swx[tid][1] = e1 / s; swx[tid][2] = e2 / s;
    }
    __syncthreads();
    if (tid < 512) {
        int k = tid >> 7, c = tid & 127;
        float x = kf[k][c];
        float kv = swx[k][0] * x;
        float fs = kv * smf[0][k][c];
        kv = swx[k][1] * kv;
        fs += kv * smf[1][k][c];
        sF[k][c] = fs;
        sF[k][128 + c] = kv;
    }
    __syncthreads();

    // ---- phase 3a: partial H over k-halves [4x256 @ 256x256, split 2] ----
    {
        const int kh = tid >> 8;           // 0/1 -> i in [kh*128, kh*128+128)
        const int c = tid & 255;
        const int ib = kh * 128;
        float acc[KPB] = {0.f, 0.f, 0.f, 0.f};
        #pragma unroll 8
        for (int i = 0; i < 128; ++i) {
            float wv = __ldg(&fw1[(ib + i) * 256 + c]);
            #pragma unroll
            for (int r = 0; r < KPB; ++r) acc[r] += sF[r][ib + i] * wv;
        }
        #pragma unroll
        for (int r = 0; r < KPB; ++r) pH[kh][r][c] = acc[r];
    }
    __syncthreads();
    // combine + BN + ReLU: 1024 outputs over 512 threads
    #pragma unroll
    for (int q = 0; q < 2; ++q) {
        int idx = tid + q * 512;
        int r = idx >> 8, c = idx & 255;
        float h = (pH[0][r][c] + pH[1][r][c]) * fg1[c] + fb1[c];
        sH[r][c] = h > 0.f ? h : 0.f;
    }
    __syncthreads();

    // ---- phase 3b: out = sH @ fw2 + b2  [4x256 @ 256x128] ----
    {
        const int c = tid & 127, r = tid >> 7;   // 4 rows, 1 output/thread
        float a = 0.f;
        #pragma unroll 8
        for (int i = 0; i < 256; ++i)
            a += sH[r][i] * __ldg(&fw2[i * 128 + c]);
        outF[OUT_OFF + (size_t)(g0 + r) * 128 + c] = a + fb2[c];
    }
}

// ---------------- launch ----------------
extern "C" void kernel_launch(void* const* d_in, const int* in_sizes, int n_in,
                              void* d_out, int out_size)
{
    const float* fusion_feat = (const float*)d_in[0];
    const float* src_feat_a  = (const float*)d_in[1];
    const float* src_feat_b  = (const float*)d_in[2];
    const float* heat_w1 = (const float*)d_in[3];
    const float* heat_g1 = (const float*)d_in[4];
    const float* heat_b1 = (const float*)d_in[5];
    const float* heat_w2 = (const float*)d_in[6];
    const float* heat_b2 = (const float*)d_in[7];
    const float* knn_w = (const float*)d_in[8];
    const float* knn_b = (const float*)d_in[9];
    const float* kw_w1 = (const float*)d_in[10];
    const float* kw_g1 = (const float*)d_in[11];
    const float* kw_b1 = (const float*)d_in[12];
    const float* kw_w2 = (const float*)d_in[13];
    const float* kw_b2 = (const float*)d_in[14];
    const float* fuse_w1 = (const float*)d_in[15];
    const float* fuse_g1 = (const float*)d_in[16];
    const float* fuse_b1 = (const float*)d_in[17];
    const float* fuse_w2 = (const float*)d_in[18];
    const float* fuse_b2 = (const float*)d_in[19];
    const int* fusion_coords = (const int*)d_in[20];
    const int* src_coords_a  = (const int*)d_in[21];
    const int* src_coords_b  = (const int*)d_in[22];
    float* outF = (float*)d_out;

    cudaFuncSetAttribute(heat_kernel, cudaFuncAttributeMaxDynamicSharedMemorySize, HEAT_SMEM);
    cudaFuncSetAttribute(topk_kernel, cudaFuncAttributeMaxDynamicSharedMemorySize, TOPK_SMEM);

    cellreset_kernel<<<(2 * B * NCELLMAX + 1023) / 1024, 1024>>>();
    heat_kernel<<<NROWS / 64, 256, HEAT_SMEM>>>(fusion_feat, heat_w1, heat_g1,
                                                heat_b1, heat_w2, heat_b2,
                                                src_coords_a, src_coords_b, outF);
    topk_kernel<<<B, 1024, TOPK_SMEM>>>(fusion_coords, outF);
    megafuse_kernel<<<NK_TOT / KPB, 512>>>(src_feat_a, src_feat_b, knn_w, knn_b,
                                           fusion_feat, kw_w1, kw_g1, kw_b1,
                                           kw_w2, kw_b2, fuse_w1, fuse_g1,
                                           fuse_b1, fuse_w2, fuse_b2, outF);
}